// round 2
// baseline (speedup 1.0000x reference)
#include <cuda_runtime.h>
#include <math.h>

// Problem dims (compile-time constants)
#define Tn 2048   // tokens = B*S
#define Hn 2048   // hidden
#define Fn 7168   // ffn
#define En 8      // experts
#define Rn 32     // lora rank
#define Kn 2      // top-k

// ---------------- scratch (device globals; no allocation allowed) ----------
__device__ float g_base1[Tn * Fn];
__device__ float g_base3[Tn * Fn];
__device__ float g_x2k0[Tn * Fn];
__device__ float g_x2k1[Tn * Fn];
__device__ float g_x2w [Tn * Fn];
__device__ int   g_sel [Tn * Kn];
__device__ float g_rw  [Tn * Kn];
__device__ float g_a1  [Tn * Kn * Rn];
__device__ float g_a3  [Tn * Kn * Rn];
__device__ float g_a2  [Tn * Kn * Rn];

__device__ __forceinline__ float warp_sum(float v) {
#pragma unroll
    for (int o = 16; o; o >>= 1) v += __shfl_xor_sync(0xffffffffu, v, o);
    return v;
}

// ---------------- K1: gate (logits, softmax-free top2 + renorm weights) ----
__global__ __launch_bounds__(256) void gate_kernel(
    const float* __restrict__ x, const float* __restrict__ Wg)
{
    int t = blockIdx.x;
    int tid = threadIdx.x;
    int w = tid >> 5, lane = tid & 31;      // 8 warps == 8 experts
    const float* xr = x + (size_t)t * Hn;
    const float* wr = Wg + (size_t)w * Hn;
    float s = 0.f;
    for (int h = lane * 4; h < Hn; h += 32 * 4) {
        float4 xv = *(const float4*)(xr + h);
        float4 wv = *(const float4*)(wr + h);
        s += xv.x * wv.x + xv.y * wv.y + xv.z * wv.z + xv.w * wv.w;
    }
    s = warp_sum(s);
    __shared__ float logits[En];
    if (lane == 0) logits[w] = s;
    __syncthreads();
    if (tid == 0) {
        int i0 = 0; float l0 = logits[0];
#pragma unroll
        for (int e = 1; e < En; e++) if (logits[e] > l0) { l0 = logits[e]; i0 = e; }
        int i1 = -1; float l1 = -3.0e38f;
#pragma unroll
        for (int e = 0; e < En; e++) if (e != i0 && logits[e] > l1) { l1 = logits[e]; i1 = e; }
        // rw0 = p0/(p0+p1) with softmax probs -> 1/(1+exp(l1-l0))
        float r0 = 1.f / (1.f + expf(l1 - l0));
        g_sel[t * 2 + 0] = i0;
        g_sel[t * 2 + 1] = i1;
        g_rw [t * 2 + 0] = r0;
        g_rw [t * 2 + 1] = 1.f - r0;
    }
}

// ---------------- K2: a1/a3 projections for the selected experts ----------
__global__ __launch_bounds__(256) void a13_kernel(
    const float* __restrict__ x, const float* __restrict__ A1,
    const float* __restrict__ A3)
{
    int t = blockIdx.x, k = blockIdx.y;
    int tid = threadIdx.x;
    int w = tid >> 5, lane = tid & 31;
    __shared__ float xs[Hn];
    const float* xr = x + (size_t)t * Hn;
    for (int h = tid * 4; h < Hn; h += 256 * 4)
        *(float4*)(xs + h) = *(const float4*)(xr + h);
    __syncthreads();
    int e = g_sel[t * 2 + k];
    for (int r = w; r < Rn; r += 8) {
        const float* a1r = A1 + ((size_t)e * Rn + r) * Hn;
        const float* a3r = A3 + ((size_t)e * Rn + r) * Hn;
        float s1 = 0.f, s3 = 0.f;
        for (int h = lane * 4; h < Hn; h += 32 * 4) {
            float4 xv = *(const float4*)(xs + h);
            float4 v1 = *(const float4*)(a1r + h);
            float4 v3 = *(const float4*)(a3r + h);
            s1 += xv.x * v1.x + xv.y * v1.y + xv.z * v1.z + xv.w * v1.w;
            s3 += xv.x * v3.x + xv.y * v3.y + xv.z * v3.z + xv.w * v3.w;
        }
        s1 = warp_sum(s1);
        s3 = warp_sum(s3);
        if (lane == 0) {
            g_a1[((size_t)t * 2 + k) * Rn + r] = s1;
            g_a3[((size_t)t * 2 + k) * Rn + r] = s3;
        }
    }
}

// ---------------- SGEMM: C[M,N] = A[M,Kd] @ B[N,Kd]^T (row-major) ----------
#define BM 128
#define BN 128
#define BK 8
#define TM 8
#define TN 8
__global__ __launch_bounds__(256) void sgemm_tn(
    const float* __restrict__ A, const float* __restrict__ B,
    float* __restrict__ C, int M, int N, int Kd)
{
    __shared__ float As[BK][BM];
    __shared__ float Bs[BK][BN];
    int bx = blockIdx.x;  // N tile
    int by = blockIdx.y;  // M tile
    int tid = threadIdx.x;
    int aRow = tid >> 1, aK = (tid & 1) * 4;
    int tx = tid & 15, ty = tid >> 4;

    const float* Ab = A + (size_t)(by * BM) * Kd;
    const float* Bb = B + (size_t)(bx * BN) * Kd;

    float acc[TM][TN];
#pragma unroll
    for (int i = 0; i < TM; i++)
#pragma unroll
        for (int j = 0; j < TN; j++) acc[i][j] = 0.f;

    for (int k0 = 0; k0 < Kd; k0 += BK) {
        float4 av = *(const float4*)(Ab + (size_t)aRow * Kd + k0 + aK);
        float4 bv = *(const float4*)(Bb + (size_t)aRow * Kd + k0 + aK);
        As[aK + 0][aRow] = av.x; As[aK + 1][aRow] = av.y;
        As[aK + 2][aRow] = av.z; As[aK + 3][aRow] = av.w;
        Bs[aK + 0][aRow] = bv.x; Bs[aK + 1][aRow] = bv.y;
        Bs[aK + 2][aRow] = bv.z; Bs[aK + 3][aRow] = bv.w;
        __syncthreads();
#pragma unroll
        for (int k = 0; k < BK; k++) {
            float4 a0 = *(const float4*)(&As[k][ty * TM]);
            float4 a1 = *(const float4*)(&As[k][ty * TM + 4]);
            float4 b0 = *(const float4*)(&Bs[k][tx * TN]);
            float4 b1 = *(const float4*)(&Bs[k][tx * TN + 4]);
            float a[TM] = {a0.x, a0.y, a0.z, a0.w, a1.x, a1.y, a1.z, a1.w};
            float b[TN] = {b0.x, b0.y, b0.z, b0.w, b1.x, b1.y, b1.z, b1.w};
#pragma unroll
            for (int i = 0; i < TM; i++)
#pragma unroll
                for (int j = 0; j < TN; j++) acc[i][j] += a[i] * b[j];
        }
        __syncthreads();
    }
#pragma unroll
    for (int i = 0; i < TM; i++) {
        float* Cr = C + (size_t)(by * BM + ty * TM + i) * N + bx * BN + tx * TN;
        float4 c0 = make_float4(acc[i][0], acc[i][1], acc[i][2], acc[i][3]);
        float4 c1 = make_float4(acc[i][4], acc[i][5], acc[i][6], acc[i][7]);
        *(float4*)(Cr) = c0;
        *(float4*)(Cr + 4) = c1;
    }
}

// ------- K4: lora1/lora3 + silu + per-k x2, weighted x2 for shared down ----
__global__ __launch_bounds__(256) void fuse_kernel(
    const float* __restrict__ B1, const float* __restrict__ B3)
{
    int t = blockIdx.x;
    int tid = threadIdx.x;
    __shared__ float a1s[Kn][Rn];
    __shared__ float a3s[Kn][Rn];
    __shared__ int   es[Kn];
    __shared__ float ws[Kn];
    if (tid < Kn * Rn) {
        ((float*)a1s)[tid] = g_a1[(size_t)t * Kn * Rn + tid];
        ((float*)a3s)[tid] = g_a3[(size_t)t * Kn * Rn + tid];
    }
    if (tid < Kn) {
        es[tid] = g_sel[t * Kn + tid];
        ws[tid] = g_rw [t * Kn + tid];
    }
    __syncthreads();
    for (int f = tid; f < Fn; f += 256) {
        float b1v = g_base1[(size_t)t * Fn + f];
        float b3v = g_base3[(size_t)t * Fn + f];
        float x2v[Kn];
#pragma unroll
        for (int k = 0; k < Kn; k++) {
            const float* b1r = B1 + ((size_t)es[k] * Fn + f) * Rn;
            const float* b3r = B3 + ((size_t)es[k] * Fn + f) * Rn;
            float l1 = 0.f, l3 = 0.f;
#pragma unroll
            for (int r = 0; r < Rn; r += 4) {
                float4 v1 = *(const float4*)(b1r + r);
                float4 v3 = *(const float4*)(b3r + r);
                l1 += v1.x * a1s[k][r] + v1.y * a1s[k][r + 1]
                    + v1.z * a1s[k][r + 2] + v1.w * a1s[k][r + 3];
                l3 += v3.x * a3s[k][r] + v3.y * a3s[k][r + 1]
                    + v3.z * a3s[k][r + 2] + v3.w * a3s[k][r + 3];
            }
            float x1 = b1v + l1;
            float x3 = b3v + l3;
            float sig = 1.f / (1.f + expf(-x1));
            x2v[k] = x1 * sig * x3;
        }
        g_x2k0[(size_t)t * Fn + f] = x2v[0];
        g_x2k1[(size_t)t * Fn + f] = x2v[1];
        g_x2w [(size_t)t * Fn + f] = ws[0] * x2v[0] + ws[1] * x2v[1];
    }
}

// ---------------- K5: a2 = x2_k @ A2[e]^T  (per token, per slot) -----------
__global__ __launch_bounds__(256) void a2_kernel(const float* __restrict__ A2)
{
    int t = blockIdx.x, k = blockIdx.y;
    int tid = threadIdx.x;
    int w = tid >> 5, lane = tid & 31;
    __shared__ float xs[Fn];   // 28KB
    const float* xr = (k == 0 ? g_x2k0 : g_x2k1) + (size_t)t * Fn;
    for (int f = tid * 4; f < Fn; f += 256 * 4)
        *(float4*)(xs + f) = *(const float4*)(xr + f);
    __syncthreads();
    int e = g_sel[t * 2 + k];
    for (int r = w; r < Rn; r += 8) {
        const float* ar = A2 + ((size_t)e * Rn + r) * Fn;
        float s = 0.f;
        for (int f = lane * 4; f < Fn; f += 32 * 4) {
            float4 xv = *(const float4*)(xs + f);
            float4 av = *(const float4*)(ar + f);
            s += xv.x * av.x + xv.y * av.y + xv.z * av.z + xv.w * av.w;
        }
        s = warp_sum(s);
        if (lane == 0) g_a2[((size_t)t * 2 + k) * Rn + r] = s;
    }
}

// ---------------- K6: out += sum_k rw_k * (B2[e_k] @ a2_k)  ----------------
__global__ __launch_bounds__(256) void final_kernel(
    const float* __restrict__ B2, float* __restrict__ out)
{
    int t = blockIdx.x;
    int tid = threadIdx.x;
    __shared__ float a2s[Kn][Rn];
    __shared__ int   es[Kn];
    __shared__ float ws[Kn];
    if (tid < Kn * Rn) ((float*)a2s)[tid] = g_a2[(size_t)t * Kn * Rn + tid];
    if (tid < Kn) {
        es[tid] = g_sel[t * Kn + tid];
        ws[tid] = g_rw [t * Kn + tid];
    }
    __syncthreads();
    for (int h = tid; h < Hn; h += 256) {
        float acc = out[(size_t)t * Hn + h];   // holds down = x2w @ W2^T
#pragma unroll
        for (int k = 0; k < Kn; k++) {
            const float* br = B2 + ((size_t)es[k] * Hn + h) * Rn;
            float l2 = 0.f;
#pragma unroll
            for (int r = 0; r < Rn; r += 4) {
                float4 bv = *(const float4*)(br + r);
                l2 += bv.x * a2s[k][r] + bv.y * a2s[k][r + 1]
                    + bv.z * a2s[k][r + 2] + bv.w * a2s[k][r + 3];
            }
            acc += ws[k] * l2;
        }
        out[(size_t)t * Hn + h] = acc;
    }
}

// ---------------------------------------------------------------------------
extern "C" void kernel_launch(void* const* d_in, const int* in_sizes, int n_in,
                              void* d_out, int out_size)
{
    (void)in_sizes; (void)n_in; (void)out_size;
    const float* x  = (const float*)d_in[0];
    const float* Wg = (const float*)d_in[1];
    const float* W1 = (const float*)d_in[2];
    const float* W2 = (const float*)d_in[3];
    const float* W3 = (const float*)d_in[4];
    const float* A1 = (const float*)d_in[5];
    const float* B1 = (const float*)d_in[6];
    const float* A2 = (const float*)d_in[7];
    const float* B2 = (const float*)d_in[8];
    const float* A3 = (const float*)d_in[9];
    const float* B3 = (const float*)d_in[10];
    float* out = (float*)d_out;

    float *base1, *base3, *x2w;
    cudaGetSymbolAddress((void**)&base1, g_base1);
    cudaGetSymbolAddress((void**)&base3, g_base3);
    cudaGetSymbolAddress((void**)&x2w,  g_x2w);

    gate_kernel<<<Tn, 256>>>(x, Wg);
    a13_kernel<<<dim3(Tn, Kn), 256>>>(x, A1, A3);
    sgemm_tn<<<dim3(Fn / BN, Tn / BM), 256>>>(x, W1, base1, Tn, Fn, Hn);
    sgemm_tn<<<dim3(Fn / BN, Tn / BM), 256>>>(x, W3, base3, Tn, Fn, Hn);
    fuse_kernel<<<Tn, 256>>>(B1, B3);
    a2_kernel<<<dim3(Tn, Kn), 256>>>(A2);
    // down GEMM writes d_out directly: out = (rw0*x2_0 + rw1*x2_1) @ W2^T
    sgemm_tn<<<dim3(Hn / BN, Tn / BM), 256>>>(x2w, W2, out, Tn, Hn, Fn);
    final_kernel<<<Tn, 256>>>(B2, out);
}

// round 4
// speedup vs baseline: 1.6909x; 1.6909x over previous
#include <cuda_runtime.h>
#include <cuda_bf16.h>
#include <math.h>
#include <stdint.h>

// Problem dims
#define Tn 2048   // tokens = B*S
#define Hn 2048   // hidden
#define Fn 7168   // ffn
#define En 8      // experts
#define Rn 32     // lora rank
#define Kn 2      // top-k

// HMMA GEMM tiling
#define GBM 128
#define GBN 128
#define KBE 64                     // bf16 K elems per stage = 128B rows (SW128)
#define STAGES 4
#define A_TILE_B (GBM * 128)       // 16384
#define B_TILE_B (GBN * 128)       // 16384
#define STAGE_B  (A_TILE_B + B_TILE_B)       // 32768
#define SMEM_TOTAL (STAGES * STAGE_B)        // 131072

#define SWZ(o) ((o) ^ (((o) >> 3) & 0x70))

// ---------------- scratch (device globals) ---------------------------------
__device__ __align__(256) float g_base1[Tn * Fn];
__device__ __align__(256) float g_base3[Tn * Fn];
__device__ __align__(256) float g_x2k0[Tn * Fn];
__device__ __align__(256) float g_x2k1[Tn * Fn];
__device__ __align__(256) __nv_bfloat16 g_xs [Tn * 3 * Hn];   // x split  [hi,hi,lo]
__device__ __align__(256) __nv_bfloat16 g_w1s[Fn * 3 * Hn];   // W1 split [hi,lo,hi]
__device__ __align__(256) __nv_bfloat16 g_w3s[Fn * 3 * Hn];   // W3 split [hi,lo,hi]
__device__ __align__(256) __nv_bfloat16 g_w2s[Hn * 3 * Fn];   // W2 split [hi,lo,hi]
__device__ __align__(256) __nv_bfloat16 g_x2s[Tn * 3 * Fn];   // weighted x2 [hi,hi,lo]
__device__ int   g_sel[Tn * Kn];
__device__ float g_rw [Tn * Kn];
__device__ float g_a1 [Tn * Kn * Rn];
__device__ float g_a3 [Tn * Kn * Rn];
__device__ float g_a2 [Tn * Kn * Rn];

// ---------------- helpers ---------------------------------------------------
__device__ __forceinline__ uint32_t smem_u32(const void* p) {
    uint32_t a;
    asm("{ .reg .u64 t; cvta.to.shared.u64 t, %1; cvt.u32.u64 %0, t; }"
        : "=r"(a) : "l"(p));
    return a;
}

__device__ __forceinline__ float warp_sum(float v) {
#pragma unroll
    for (int o = 16; o; o >>= 1) v += __shfl_xor_sync(0xffffffffu, v, o);
    return v;
}

#define LDSM4(r0, r1, r2, r3, addr) \
    asm volatile("ldmatrix.sync.aligned.m8n8.x4.shared.b16 {%0,%1,%2,%3}, [%4];" \
                 : "=r"(r0), "=r"(r1), "=r"(r2), "=r"(r3) : "r"(addr))

#define MMA16816(c, a, b0, b1) \
    asm volatile("mma.sync.aligned.m16n8k16.row.col.f32.bf16.bf16.f32 " \
                 "{%0,%1,%2,%3}, {%4,%5,%6,%7}, {%8,%9}, {%0,%1,%2,%3};" \
                 : "+f"((c)[0]), "+f"((c)[1]), "+f"((c)[2]), "+f"((c)[3]) \
                 : "r"((a)[0]), "r"((a)[1]), "r"((a)[2]), "r"((a)[3]), \
                   "r"(b0), "r"(b1))

// ---------------- bf16 hi/lo split kernels ---------------------------------
// mode 0 (A side): [hi, hi, lo]; mode 1 (B side): [hi, lo, hi]
__global__ __launch_bounds__(256) void split_kernel(
    const float* __restrict__ src, __nv_bfloat16* __restrict__ dst,
    int rows, int cols, int bmode)
{
    size_t n = (size_t)rows * cols;
    for (size_t i = (size_t)blockIdx.x * blockDim.x + threadIdx.x; i < n;
         i += (size_t)gridDim.x * blockDim.x) {
        size_t r = i / cols;
        int c = (int)(i - r * cols);
        float v = src[i];
        __nv_bfloat16 hi = __float2bfloat16(v);
        __nv_bfloat16 lo = __float2bfloat16(v - __bfloat162float(hi));
        __nv_bfloat16* d = dst + r * (size_t)(3 * cols) + c;
        d[0] = hi;
        d[cols]     = bmode ? lo : hi;
        d[2 * cols] = bmode ? hi : lo;
    }
}

// ---------------- stage loader (cp.async, SW128 layout) --------------------
__device__ __forceinline__ void load_stage(
    uint32_t sb, const __nv_bfloat16* Ab, const __nv_bfloat16* Bb,
    int Kp, int it, int stage, int tid)
{
    uint32_t st = sb + stage * STAGE_B;
    int k0 = it * KBE;
#pragma unroll
    for (int i = 0; i < 8; i++) {
        int c = tid + i * 256;          // 0..2047
        uint32_t soff;
        const __nv_bfloat16* g;
        if (c < 1024) {                 // A: 128 rows x 8 chunks
            int row = c >> 3, j = c & 7;
            soff = st + SWZ(row * 128 + j * 16);
            g = Ab + (size_t)row * Kp + k0 + j * 8;
        } else {                        // B: 128 rows x 8 chunks
            int cc = c - 1024;
            int row = cc >> 3, j = cc & 7;
            soff = st + A_TILE_B + SWZ(row * 128 + j * 16);
            g = Bb + (size_t)row * Kp + k0 + j * 8;
        }
        asm volatile("cp.async.cg.shared.global [%0], [%1], 16;"
                     :: "r"(soff), "l"(g) : "memory");
    }
}

// ---------------- HMMA bf16 GEMM: C[M,N] = A[M,Kp] @ B[N,Kp]^T -------------
__global__ __launch_bounds__(256, 1) void gemm_bf16(
    const __nv_bfloat16* __restrict__ A, const __nv_bfloat16* __restrict__ B,
    float* __restrict__ C, int N, int Kp)
{
    extern __shared__ __align__(1024) char smem[];
    uint32_t sb = smem_u32(smem);
    int tid = threadIdx.x, wid = tid >> 5, lane = tid & 31;
    int wm = wid & 3, wn = wid >> 2;       // 4 warps in M, 2 in N
    int bx = blockIdx.x, by = blockIdx.y;
    const int niter = Kp / KBE;

    const __nv_bfloat16* Ab = A + (size_t)(by * GBM) * Kp;
    const __nv_bfloat16* Bb = B + (size_t)(bx * GBN) * Kp;

    // prologue: fill STAGES-1 stages
#pragma unroll
    for (int it = 0; it < STAGES - 1; it++) {
        load_stage(sb, Ab, Bb, Kp, it, it, tid);
        asm volatile("cp.async.commit_group;" ::: "memory");
    }

    float acc[2][8][4];
#pragma unroll
    for (int mi = 0; mi < 2; mi++)
#pragma unroll
        for (int nj = 0; nj < 8; nj++)
#pragma unroll
            for (int q = 0; q < 4; q++) acc[mi][nj][q] = 0.f;

    // per-lane ldmatrix row bases (within a stage tile)
    int gq = lane >> 3, rr = lane & 7;
    int kc = gq >> 1;                      // 0/1: which 16B k-chunk half
    uint32_t aRow[2]; int aXor[2];
#pragma unroll
    for (int mi = 0; mi < 2; mi++) {
        int m = wm * 32 + mi * 16 + (gq & 1) * 8 + rr;
        aRow[mi] = (uint32_t)(m * 128);
        aXor[mi] = m & 7;
    }
    uint32_t bRow[4]; int bXor[4];
#pragma unroll
    for (int ni = 0; ni < 4; ni++) {
        int n = wn * 64 + ni * 16 + (gq & 1) * 8 + rr;
        bRow[ni] = (uint32_t)(A_TILE_B + n * 128);
        bXor[ni] = n & 7;
    }

    for (int it = 0; it < niter; it++) {
        int s = it & (STAGES - 1);
        asm volatile("cp.async.wait_group %0;" :: "n"(STAGES - 2) : "memory");
        __syncthreads();
        int jt = it + STAGES - 1;
        if (jt < niter)
            load_stage(sb, Ab, Bb, Kp, jt, jt & (STAGES - 1), tid);
        asm volatile("cp.async.commit_group;" ::: "memory");

        uint32_t stb = sb + s * STAGE_B;
#pragma unroll
        for (int ks = 0; ks < 4; ks++) {
            uint32_t a[2][4];
#pragma unroll
            for (int mi = 0; mi < 2; mi++) {
                uint32_t ad = stb + aRow[mi]
                            + (uint32_t)((((ks << 1) + kc) ^ aXor[mi]) << 4);
                LDSM4(a[mi][0], a[mi][1], a[mi][2], a[mi][3], ad);
            }
            uint32_t b[4][4];
#pragma unroll
            for (int ni = 0; ni < 4; ni++) {
                uint32_t bd = stb + bRow[ni]
                            + (uint32_t)((((ks << 1) + kc) ^ bXor[ni]) << 4);
                LDSM4(b[ni][0], b[ni][1], b[ni][2], b[ni][3], bd);
            }
#pragma unroll
            for (int mi = 0; mi < 2; mi++)
#pragma unroll
                for (int ni = 0; ni < 4; ni++) {
                    MMA16816(acc[mi][ni * 2],     a[mi], b[ni][0], b[ni][2]);
                    MMA16816(acc[mi][ni * 2 + 1], a[mi], b[ni][1], b[ni][3]);
                }
        }
        __syncthreads();
    }

    // epilogue
    int gid = lane >> 2, tig = lane & 3;
#pragma unroll
    for (int mi = 0; mi < 2; mi++) {
        int row = by * GBM + wm * 32 + mi * 16 + gid;
#pragma unroll
        for (int nj = 0; nj < 8; nj++) {
            float* p = C + (size_t)row * N + bx * GBN + wn * 64 + nj * 8 + tig * 2;
            float2 v0 = make_float2(acc[mi][nj][0], acc[mi][nj][1]);
            float2 v1 = make_float2(acc[mi][nj][2], acc[mi][nj][3]);
            *(float2*)p = v0;
            *(float2*)(p + (size_t)8 * N) = v1;
        }
    }
}

// ---------------- K1: gate -------------------------------------------------
__global__ __launch_bounds__(256) void gate_kernel(
    const float* __restrict__ x, const float* __restrict__ Wg)
{
    int t = blockIdx.x;
    int tid = threadIdx.x;
    int w = tid >> 5, lane = tid & 31;
    const float* xr = x + (size_t)t * Hn;
    const float* wr = Wg + (size_t)w * Hn;
    float s = 0.f;
    for (int h = lane * 4; h < Hn; h += 32 * 4) {
        float4 xv = *(const float4*)(xr + h);
        float4 wv = *(const float4*)(wr + h);
        s += xv.x * wv.x + xv.y * wv.y + xv.z * wv.z + xv.w * wv.w;
    }
    s = warp_sum(s);
    __shared__ float logits[En];
    if (lane == 0) logits[w] = s;
    __syncthreads();
    if (tid == 0) {
        int i0 = 0; float l0 = logits[0];
#pragma unroll
        for (int e = 1; e < En; e++) if (logits[e] > l0) { l0 = logits[e]; i0 = e; }
        int i1 = -1; float l1 = -3.0e38f;
#pragma unroll
        for (int e = 0; e < En; e++) if (e != i0 && logits[e] > l1) { l1 = logits[e]; i1 = e; }
        float r0 = 1.f / (1.f + expf(l1 - l0));
        g_sel[t * 2 + 0] = i0;
        g_sel[t * 2 + 1] = i1;
        g_rw [t * 2 + 0] = r0;
        g_rw [t * 2 + 1] = 1.f - r0;
    }
}

// ---------------- K2: a1/a3 projections ------------------------------------
__global__ __launch_bounds__(256) void a13_kernel(
    const float* __restrict__ x, const float* __restrict__ A1,
    const float* __restrict__ A3)
{
    int t = blockIdx.x, k = blockIdx.y;
    int tid = threadIdx.x;
    int w = tid >> 5, lane = tid & 31;
    __shared__ float xs[Hn];
    const float* xr = x + (size_t)t * Hn;
    for (int h = tid * 4; h < Hn; h += 256 * 4)
        *(float4*)(xs + h) = *(const float4*)(xr + h);
    __syncthreads();
    int e = g_sel[t * 2 + k];
    for (int r = w; r < Rn; r += 8) {
        const float* a1r = A1 + ((size_t)e * Rn + r) * Hn;
        const float* a3r = A3 + ((size_t)e * Rn + r) * Hn;
        float s1 = 0.f, s3 = 0.f;
        for (int h = lane * 4; h < Hn; h += 32 * 4) {
            float4 xv = *(const float4*)(xs + h);
            float4 v1 = *(const float4*)(a1r + h);
            float4 v3 = *(const float4*)(a3r + h);
            s1 += xv.x * v1.x + xv.y * v1.y + xv.z * v1.z + xv.w * v1.w;
            s3 += xv.x * v3.x + xv.y * v3.y + xv.z * v3.z + xv.w * v3.w;
        }
        s1 = warp_sum(s1);
        s3 = warp_sum(s3);
        if (lane == 0) {
            g_a1[((size_t)t * 2 + k) * Rn + r] = s1;
            g_a3[((size_t)t * 2 + k) * Rn + r] = s3;
        }
    }
}

// ------- K4: lora1/lora3 + silu + per-k x2 + weighted-x2 bf16 split --------
__global__ __launch_bounds__(256) void fuse_kernel(
    const float* __restrict__ B1, const float* __restrict__ B3)
{
    int t = blockIdx.x;
    int tid = threadIdx.x;
    __shared__ float a1s[Kn][Rn];
    __shared__ float a3s[Kn][Rn];
    __shared__ int   es[Kn];
    __shared__ float ws[Kn];
    if (tid < Kn * Rn) {
        ((float*)a1s)[tid] = g_a1[(size_t)t * Kn * Rn + tid];
        ((float*)a3s)[tid] = g_a3[(size_t)t * Kn * Rn + tid];
    }
    if (tid < Kn) {
        es[tid] = g_sel[t * Kn + tid];
        ws[tid] = g_rw [t * Kn + tid];
    }
    __syncthreads();
    for (int f = tid; f < Fn; f += 256) {
        float b1v = g_base1[(size_t)t * Fn + f];
        float b3v = g_base3[(size_t)t * Fn + f];
        float x2v[Kn];
#pragma unroll
        for (int k = 0; k < Kn; k++) {
            const float* b1r = B1 + ((size_t)es[k] * Fn + f) * Rn;
            const float* b3r = B3 + ((size_t)es[k] * Fn + f) * Rn;
            float l1 = 0.f, l3 = 0.f;
#pragma unroll
            for (int r = 0; r < Rn; r += 4) {
                float4 v1 = *(const float4*)(b1r + r);
                float4 v3 = *(const float4*)(b3r + r);
                l1 += v1.x * a1s[k][r] + v1.y * a1s[k][r + 1]
                    + v1.z * a1s[k][r + 2] + v1.w * a1s[k][r + 3];
                l3 += v3.x * a3s[k][r] + v3.y * a3s[k][r + 1]
                    + v3.z * a3s[k][r + 2] + v3.w * a3s[k][r + 3];
            }
            float x1 = b1v + l1;
            float x3 = b3v + l3;
            float sig = 1.f / (1.f + expf(-x1));
            x2v[k] = x1 * sig * x3;
        }
        g_x2k0[(size_t)t * Fn + f] = x2v[0];
        g_x2k1[(size_t)t * Fn + f] = x2v[1];
        float v = ws[0] * x2v[0] + ws[1] * x2v[1];
        __nv_bfloat16 hi = __float2bfloat16(v);
        __nv_bfloat16 lo = __float2bfloat16(v - __bfloat162float(hi));
        __nv_bfloat16* d = g_x2s + (size_t)t * 3 * Fn + f;
        d[0] = hi;
        d[Fn] = hi;
        d[2 * Fn] = lo;
    }
}

// ---------------- K5: a2 = x2_k @ A2[e]^T ----------------------------------
__global__ __launch_bounds__(256) void a2_kernel(const float* __restrict__ A2)
{
    int t = blockIdx.x, k = blockIdx.y;
    int tid = threadIdx.x;
    int w = tid >> 5, lane = tid & 31;
    __shared__ float xs[Fn];
    const float* xr = (k == 0 ? g_x2k0 : g_x2k1) + (size_t)t * Fn;
    for (int f = tid * 4; f < Fn; f += 256 * 4)
        *(float4*)(xs + f) = *(const float4*)(xr + f);
    __syncthreads();
    int e = g_sel[t * 2 + k];
    for (int r = w; r < Rn; r += 8) {
        const float* ar = A2 + ((size_t)e * Rn + r) * Fn;
        float s = 0.f;
        for (int f = lane * 4; f < Fn; f += 32 * 4) {
            float4 xv = *(const float4*)(xs + f);
            float4 av = *(const float4*)(ar + f);
            s += xv.x * av.x + xv.y * av.y + xv.z * av.z + xv.w * av.w;
        }
        s = warp_sum(s);
        if (lane == 0) g_a2[((size_t)t * 2 + k) * Rn + r] = s;
    }
}

// ---------------- K6: out += sum_k rw_k * (B2[e_k] @ a2_k) -----------------
__global__ __launch_bounds__(256) void final_kernel(
    const float* __restrict__ B2, float* __restrict__ out)
{
    int t = blockIdx.x;
    int tid = threadIdx.x;
    __shared__ float a2s[Kn][Rn];
    __shared__ int   es[Kn];
    __shared__ float ws[Kn];
    if (tid < Kn * Rn) ((float*)a2s)[tid] = g_a2[(size_t)t * Kn * Rn + tid];
    if (tid < Kn) {
        es[tid] = g_sel[t * Kn + tid];
        ws[tid] = g_rw [t * Kn + tid];
    }
    __syncthreads();
    for (int h = tid; h < Hn; h += 256) {
        float acc = out[(size_t)t * Hn + h];   // holds down GEMM result
#pragma unroll
        for (int k = 0; k < Kn; k++) {
            const float* br = B2 + ((size_t)es[k] * Hn + h) * Rn;
            float l2 = 0.f;
#pragma unroll
            for (int r = 0; r < Rn; r += 4) {
                float4 bv = *(const float4*)(br + r);
                l2 += bv.x * a2s[k][r] + bv.y * a2s[k][r + 1]
                    + bv.z * a2s[k][r + 2] + bv.w * a2s[k][r + 3];
            }
            acc += ws[k] * l2;
        }
        out[(size_t)t * Hn + h] = acc;
    }
}

// ---------------------------------------------------------------------------
extern "C" void kernel_launch(void* const* d_in, const int* in_sizes, int n_in,
                              void* d_out, int out_size)
{
    (void)in_sizes; (void)n_in; (void)out_size;
    const float* x  = (const float*)d_in[0];
    const float* Wg = (const float*)d_in[1];
    const float* W1 = (const float*)d_in[2];
    const float* W2 = (const float*)d_in[3];
    const float* W3 = (const float*)d_in[4];
    const float* A1 = (const float*)d_in[5];
    const float* B1 = (const float*)d_in[6];
    const float* A2 = (const float*)d_in[7];
    const float* B2 = (const float*)d_in[8];
    const float* A3 = (const float*)d_in[9];
    const float* B3 = (const float*)d_in[10];
    float* out = (float*)d_out;

    float *base1, *base3;
    __nv_bfloat16 *xs, *w1s, *w3s, *w2s, *x2s;
    cudaGetSymbolAddress((void**)&base1, g_base1);
    cudaGetSymbolAddress((void**)&base3, g_base3);
    cudaGetSymbolAddress((void**)&xs,  g_xs);
    cudaGetSymbolAddress((void**)&w1s, g_w1s);
    cudaGetSymbolAddress((void**)&w3s, g_w3s);
    cudaGetSymbolAddress((void**)&w2s, g_w2s);
    cudaGetSymbolAddress((void**)&x2s, g_x2s);

    cudaFuncSetAttribute(gemm_bf16, cudaFuncAttributeMaxDynamicSharedMemorySize,
                         SMEM_TOTAL);

    gate_kernel<<<Tn, 256>>>(x, Wg);
    a13_kernel<<<dim3(Tn, Kn), 256>>>(x, A1, A3);

    // bf16 hi/lo splits
    split_kernel<<<2048, 256>>>(x,  xs,  Tn, Hn, 0);   // A side [hi,hi,lo]
    split_kernel<<<2048, 256>>>(W1, w1s, Fn, Hn, 1);   // B side [hi,lo,hi]
    split_kernel<<<2048, 256>>>(W3, w3s, Fn, Hn, 1);
    split_kernel<<<2048, 256>>>(W2, w2s, Hn, Fn, 1);

    // base1 = x @ W1^T, base3 = x @ W3^T   (HMMA, K' = 3*Hn)
    gemm_bf16<<<dim3(Fn / GBN, Tn / GBM), 256, SMEM_TOTAL>>>(xs, w1s, base1, Fn, 3 * Hn);
    gemm_bf16<<<dim3(Fn / GBN, Tn / GBM), 256, SMEM_TOTAL>>>(xs, w3s, base3, Fn, 3 * Hn);

    fuse_kernel<<<Tn, 256>>>(B1, B3);
    a2_kernel<<<dim3(Tn, Kn), 256>>>(A2);

    // down GEMM directly into d_out: out = (rw0*x2_0 + rw1*x2_1) @ W2^T
    gemm_bf16<<<dim3(Hn / GBN, Tn / GBM), 256, SMEM_TOTAL>>>(x2s, w2s, out, Hn, 3 * Fn);

    final_kernel<<<Tn, 256>>>(B2, out);
}

// round 5
// speedup vs baseline: 2.0628x; 1.2200x over previous
#include <cuda_runtime.h>
#include <cuda_bf16.h>
#include <math.h>
#include <stdint.h>

// Problem dims
#define Tn 2048   // tokens = B*S
#define Hn 2048   // hidden
#define Fn 7168   // ffn
#define En 8      // experts
#define Rn 32     // lora rank
#define Kn 2      // top-k

// HMMA GEMM tiling
#define GBM 128
#define GBN 128
#define KBE 64                     // bf16 K elems per stage = 128B rows (SW128)
#define STAGES 4
#define A_TILE_B (GBM * 128)       // 16384
#define B_TILE_B (GBN * 128)       // 16384
#define STAGE_B  (A_TILE_B + B_TILE_B)       // 32768
#define SMEM_TOTAL (STAGES * STAGE_B)        // 131072

#define SWZ(o) ((o) ^ (((o) >> 3) & 0x70))

// ---------------- scratch (device globals) ---------------------------------
__device__ __align__(256) float g_base1[Tn * Fn];
__device__ __align__(256) float g_base3[Tn * Fn];
__device__ __align__(256) float g_x2k0[Tn * Fn];
__device__ __align__(256) float g_x2k1[Tn * Fn];
__device__ __align__(256) float g_l2k0[Tn * Hn];
__device__ __align__(256) float g_l2k1[Tn * Hn];
__device__ __align__(256) __nv_bfloat16 g_xs [Tn * 3 * Hn];   // x split  [hi,hi,lo]
__device__ __align__(256) __nv_bfloat16 g_w1s[Fn * 3 * Hn];   // W1 split [hi,lo,hi]
__device__ __align__(256) __nv_bfloat16 g_w3s[Fn * 3 * Hn];   // W3 split [hi,lo,hi]
__device__ __align__(256) __nv_bfloat16 g_w2s[Hn * 3 * Fn];   // W2 split [hi,lo,hi]
__device__ __align__(256) __nv_bfloat16 g_x2s[Tn * 3 * Fn];   // weighted x2 [hi,hi,lo]
__device__ int   g_sel[Tn * Kn];
__device__ float g_rw [Tn * Kn];
__device__ float g_a1 [Tn * Kn * Rn];
__device__ float g_a3 [Tn * Kn * Rn];
__device__ float g_a2 [Tn * Kn * Rn];
// expert grouping
__device__ int g_off [En + 1];
__device__ int g_cur [En];
__device__ int g_list[Tn * Kn];

// ---------------- helpers ---------------------------------------------------
__device__ __forceinline__ uint32_t smem_u32(const void* p) {
    uint32_t a;
    asm("{ .reg .u64 t; cvta.to.shared.u64 t, %1; cvt.u32.u64 %0, t; }"
        : "=r"(a) : "l"(p));
    return a;
}

__device__ __forceinline__ float warp_sum(float v) {
#pragma unroll
    for (int o = 16; o; o >>= 1) v += __shfl_xor_sync(0xffffffffu, v, o);
    return v;
}

// find (expert, chunk) for this block given chunk size CH; returns false if idle
__device__ __forceinline__ bool find_chunk(int b, int CH, int& e, int& start,
                                           int& nent) {
    int acc = 0;
    for (int ee = 0; ee < En; ee++) {
        int o0 = g_off[ee], o1 = g_off[ee + 1];
        int cnt = o1 - o0;
        int nch = (cnt + CH - 1) / CH;
        if (b < acc + nch) {
            e = ee;
            start = o0 + (b - acc) * CH;
            nent = min(CH, o1 - start);
            return true;
        }
        acc += nch;
    }
    return false;
}

#define LDSM4(r0, r1, r2, r3, addr) \
    asm volatile("ldmatrix.sync.aligned.m8n8.x4.shared.b16 {%0,%1,%2,%3}, [%4];" \
                 : "=r"(r0), "=r"(r1), "=r"(r2), "=r"(r3) : "r"(addr))

#define MMA16816(c, a, b0, b1) \
    asm volatile("mma.sync.aligned.m16n8k16.row.col.f32.bf16.bf16.f32 " \
                 "{%0,%1,%2,%3}, {%4,%5,%6,%7}, {%8,%9}, {%0,%1,%2,%3};" \
                 : "+f"((c)[0]), "+f"((c)[1]), "+f"((c)[2]), "+f"((c)[3]) \
                 : "r"((a)[0]), "r"((a)[1]), "r"((a)[2]), "r"((a)[3]), \
                   "r"(b0), "r"(b1))

// ---------------- bf16 hi/lo split -----------------------------------------
__global__ __launch_bounds__(256) void split_kernel(
    const float* __restrict__ src, __nv_bfloat16* __restrict__ dst,
    int rows, int cols, int bmode)
{
    size_t n = (size_t)rows * cols;
    for (size_t i = (size_t)blockIdx.x * blockDim.x + threadIdx.x; i < n;
         i += (size_t)gridDim.x * blockDim.x) {
        size_t r = i / cols;
        int c = (int)(i - r * cols);
        float v = src[i];
        __nv_bfloat16 hi = __float2bfloat16(v);
        __nv_bfloat16 lo = __float2bfloat16(v - __bfloat162float(hi));
        __nv_bfloat16* d = dst + r * (size_t)(3 * cols) + c;
        d[0] = hi;
        d[cols]     = bmode ? lo : hi;
        d[2 * cols] = bmode ? hi : lo;
    }
}

// ---------------- GEMM stage loader (cp.async, SW128) ----------------------
__device__ __forceinline__ void load_stage(
    uint32_t sb, const __nv_bfloat16* Ab, const __nv_bfloat16* Bb,
    int Kp, int it, int stage, int tid)
{
    uint32_t st = sb + stage * STAGE_B;
    int k0 = it * KBE;
#pragma unroll
    for (int i = 0; i < 8; i++) {
        int c = tid + i * 256;
        uint32_t soff;
        const __nv_bfloat16* g;
        if (c < 1024) {
            int row = c >> 3, j = c & 7;
            soff = st + SWZ(row * 128 + j * 16);
            g = Ab + (size_t)row * Kp + k0 + j * 8;
        } else {
            int cc = c - 1024;
            int row = cc >> 3, j = cc & 7;
            soff = st + A_TILE_B + SWZ(row * 128 + j * 16);
            g = Bb + (size_t)row * Kp + k0 + j * 8;
        }
        asm volatile("cp.async.cg.shared.global [%0], [%1], 16;"
                     :: "r"(soff), "l"(g) : "memory");
    }
}

// ---------------- HMMA bf16 GEMM: C[M,N] = A[M,Kp] @ B[N,Kp]^T -------------
__global__ __launch_bounds__(256, 1) void gemm_bf16(
    const __nv_bfloat16* __restrict__ A, const __nv_bfloat16* __restrict__ B,
    float* __restrict__ C, int N, int Kp)
{
    extern __shared__ __align__(1024) char smem[];
    uint32_t sb = smem_u32(smem);
    int tid = threadIdx.x, wid = tid >> 5, lane = tid & 31;
    int wm = wid & 3, wn = wid >> 2;
    int bx = blockIdx.x, by = blockIdx.y;
    const int niter = Kp / KBE;

    const __nv_bfloat16* Ab = A + (size_t)(by * GBM) * Kp;
    const __nv_bfloat16* Bb = B + (size_t)(bx * GBN) * Kp;

#pragma unroll
    for (int it = 0; it < STAGES - 1; it++) {
        load_stage(sb, Ab, Bb, Kp, it, it, tid);
        asm volatile("cp.async.commit_group;" ::: "memory");
    }

    float acc[2][8][4];
#pragma unroll
    for (int mi = 0; mi < 2; mi++)
#pragma unroll
        for (int nj = 0; nj < 8; nj++)
#pragma unroll
            for (int q = 0; q < 4; q++) acc[mi][nj][q] = 0.f;

    int gq = lane >> 3, rr = lane & 7;
    int kc = gq >> 1;
    uint32_t aRow[2]; int aXor[2];
#pragma unroll
    for (int mi = 0; mi < 2; mi++) {
        int m = wm * 32 + mi * 16 + (gq & 1) * 8 + rr;
        aRow[mi] = (uint32_t)(m * 128);
        aXor[mi] = m & 7;
    }
    uint32_t bRow[4]; int bXor[4];
#pragma unroll
    for (int ni = 0; ni < 4; ni++) {
        int n = wn * 64 + ni * 16 + (gq & 1) * 8 + rr;
        bRow[ni] = (uint32_t)(A_TILE_B + n * 128);
        bXor[ni] = n & 7;
    }

    for (int it = 0; it < niter; it++) {
        int s = it & (STAGES - 1);
        asm volatile("cp.async.wait_group %0;" :: "n"(STAGES - 2) : "memory");
        __syncthreads();
        int jt = it + STAGES - 1;
        if (jt < niter)
            load_stage(sb, Ab, Bb, Kp, jt, jt & (STAGES - 1), tid);
        asm volatile("cp.async.commit_group;" ::: "memory");

        uint32_t stb = sb + s * STAGE_B;
#pragma unroll
        for (int ks = 0; ks < 4; ks++) {
            uint32_t a[2][4];
#pragma unroll
            for (int mi = 0; mi < 2; mi++) {
                uint32_t ad = stb + aRow[mi]
                            + (uint32_t)((((ks << 1) + kc) ^ aXor[mi]) << 4);
                LDSM4(a[mi][0], a[mi][1], a[mi][2], a[mi][3], ad);
            }
            uint32_t b[4][4];
#pragma unroll
            for (int ni = 0; ni < 4; ni++) {
                uint32_t bd = stb + bRow[ni]
                            + (uint32_t)((((ks << 1) + kc) ^ bXor[ni]) << 4);
                LDSM4(b[ni][0], b[ni][1], b[ni][2], b[ni][3], bd);
            }
#pragma unroll
            for (int mi = 0; mi < 2; mi++)
#pragma unroll
                for (int ni = 0; ni < 4; ni++) {
                    MMA16816(acc[mi][ni * 2],     a[mi], b[ni][0], b[ni][2]);
                    MMA16816(acc[mi][ni * 2 + 1], a[mi], b[ni][1], b[ni][3]);
                }
        }
        __syncthreads();
    }

    int gid = lane >> 2, tig = lane & 3;
#pragma unroll
    for (int mi = 0; mi < 2; mi++) {
        int row = by * GBM + wm * 32 + mi * 16 + gid;
#pragma unroll
        for (int nj = 0; nj < 8; nj++) {
            float* p = C + (size_t)row * N + bx * GBN + wn * 64 + nj * 8 + tig * 2;
            *(float2*)p = make_float2(acc[mi][nj][0], acc[mi][nj][1]);
            *(float2*)(p + (size_t)8 * N) = make_float2(acc[mi][nj][2], acc[mi][nj][3]);
        }
    }
}

// ---------------- K1: gate -------------------------------------------------
__global__ __launch_bounds__(256) void gate_kernel(
    const float* __restrict__ x, const float* __restrict__ Wg)
{
    int t = blockIdx.x;
    int tid = threadIdx.x;
    int w = tid >> 5, lane = tid & 31;
    const float* xr = x + (size_t)t * Hn;
    const float* wr = Wg + (size_t)w * Hn;
    float s = 0.f;
    for (int h = lane * 4; h < Hn; h += 32 * 4) {
        float4 xv = *(const float4*)(xr + h);
        float4 wv = *(const float4*)(wr + h);
        s += xv.x * wv.x + xv.y * wv.y + xv.z * wv.z + xv.w * wv.w;
    }
    s = warp_sum(s);
    __shared__ float logits[En];
    if (lane == 0) logits[w] = s;
    __syncthreads();
    if (tid == 0) {
        int i0 = 0; float l0 = logits[0];
#pragma unroll
        for (int e = 1; e < En; e++) if (logits[e] > l0) { l0 = logits[e]; i0 = e; }
        int i1 = -1; float l1 = -3.0e38f;
#pragma unroll
        for (int e = 0; e < En; e++) if (e != i0 && logits[e] > l1) { l1 = logits[e]; i1 = e; }
        float r0 = 1.f / (1.f + expf(l1 - l0));
        g_sel[t * 2 + 0] = i0;
        g_sel[t * 2 + 1] = i1;
        g_rw [t * 2 + 0] = r0;
        g_rw [t * 2 + 1] = 1.f - r0;
    }
}

// ---------------- expert grouping: histogram + scatter ---------------------
__global__ __launch_bounds__(256) void hist_kernel()
{
    __shared__ int hc[En];
    int tid = threadIdx.x;
    if (tid < En) hc[tid] = 0;
    __syncthreads();
    for (int i = tid; i < Tn * Kn; i += 256)
        atomicAdd(&hc[g_sel[i]], 1);
    __syncthreads();
    if (tid == 0) {
        int off = 0;
        for (int e = 0; e < En; e++) {
            g_off[e] = off;
            g_cur[e] = off;
            off += hc[e];
        }
        g_off[En] = off;
    }
}

__global__ __launch_bounds__(256) void scatter_kernel()
{
    int i = blockIdx.x * 256 + threadIdx.x;
    if (i < Tn * Kn) {
        int e = g_sel[i];
        int pos = atomicAdd(&g_cur[e], 1);
        g_list[pos] = i;
    }
}

// -------- grouped a1/a3: a1[id][r] = x[t] . A1[e][r]  (CH=16 entries) ------
#define CHA 16
__global__ __launch_bounds__(256) void a13_grouped(
    const float* __restrict__ x, const float* __restrict__ A1,
    const float* __restrict__ A3)
{
    int e, start, nent;
    if (!find_chunk(blockIdx.x, CHA, e, start, nent)) return;
    __shared__ float xs[CHA][129];
    __shared__ float as[64][129];
    __shared__ int ids[CHA];
    int tid = threadIdx.x;
    if (tid < CHA)
        ids[tid] = (tid < nent) ? g_list[start + tid] : g_list[start];
    __syncthreads();

    int entry = tid >> 4, rg = tid & 15;
    float acc[4] = {0.f, 0.f, 0.f, 0.f};
    int myid = ids[entry];

    for (int h0 = 0; h0 < Hn; h0 += 128) {
        // load x rows (16 x 128)
#pragma unroll
        for (int i = 0; i < 8; i++) {
            int q = tid + i * 256;
            int row = q >> 7, col = q & 127;
            xs[row][col] = x[(size_t)(ids[row] >> 1) * Hn + h0 + col];
        }
        // load A rows (64 x 128): rows 0-31 A1, 32-63 A3
#pragma unroll
        for (int i = 0; i < 32; i++) {
            int q = tid + i * 256;
            int row = q >> 7, col = q & 127;
            const float* src = (row < 32)
                ? A1 + ((size_t)(e * Rn + row) * Hn + h0 + col)
                : A3 + ((size_t)(e * Rn + row - 32) * Hn + h0 + col);
            as[row][col] = *src;
        }
        __syncthreads();
#pragma unroll 4
        for (int h = 0; h < 128; h++) {
            float xv = xs[entry][h];
#pragma unroll
            for (int j = 0; j < 4; j++)
                acc[j] += xv * as[rg + 16 * j][h];
        }
        __syncthreads();
    }
    if (entry < nent) {
#pragma unroll
        for (int j = 0; j < 4; j++) {
            int rhat = rg + 16 * j;
            if (rhat < 32) g_a1[(size_t)myid * Rn + rhat] = acc[j];
            else           g_a3[(size_t)myid * Rn + rhat - 32] = acc[j];
        }
    }
}

// -------- grouped fuse: x2_k = silu(base1+B1.a1)*(base3+B3.a3)  (CH=32) ----
#define CHF 32
__global__ __launch_bounds__(256) void fuse_grouped(
    const float* __restrict__ B1, const float* __restrict__ B3)
{
    int e, start, nent;
    if (!find_chunk(blockIdx.x, CHF, e, start, nent)) return;
    __shared__ float a1s[CHF][Rn];
    __shared__ float a3s[CHF][Rn];
    __shared__ int ids[CHF];
    int tid = threadIdx.x;
    if (tid < CHF)
        ids[tid] = (tid < nent) ? g_list[start + tid] : g_list[start];
    __syncthreads();
#pragma unroll
    for (int i = 0; i < 4; i++) {
        int q = tid + i * 256;
        int en = q >> 5, r = q & 31;
        int id = ids[en];
        a1s[en][r] = g_a1[(size_t)id * Rn + r];
        a3s[en][r] = g_a3[(size_t)id * Rn + r];
    }
    __syncthreads();

    for (int f0 = 0; f0 < Fn; f0 += 256) {
        int f = f0 + tid;
        float b1r[Rn], b3r[Rn];
        const float4* p1 = (const float4*)(B1 + ((size_t)e * Fn + f) * Rn);
        const float4* p3 = (const float4*)(B3 + ((size_t)e * Fn + f) * Rn);
#pragma unroll
        for (int q = 0; q < 8; q++) {
            float4 v1 = p1[q], v3 = p3[q];
            b1r[q * 4 + 0] = v1.x; b1r[q * 4 + 1] = v1.y;
            b1r[q * 4 + 2] = v1.z; b1r[q * 4 + 3] = v1.w;
            b3r[q * 4 + 0] = v3.x; b3r[q * 4 + 1] = v3.y;
            b3r[q * 4 + 2] = v3.z; b3r[q * 4 + 3] = v3.w;
        }
        for (int en = 0; en < nent; en++) {
            int id = ids[en];
            int t = id >> 1, kk = id & 1;
            float l1 = 0.f, l3 = 0.f;
#pragma unroll
            for (int r = 0; r < Rn; r++) {
                l1 += b1r[r] * a1s[en][r];
                l3 += b3r[r] * a3s[en][r];
            }
            float x1 = g_base1[(size_t)t * Fn + f] + l1;
            float x3 = g_base3[(size_t)t * Fn + f] + l3;
            float sig = 1.f / (1.f + expf(-x1));
            float x2 = x1 * sig * x3;
            (kk ? g_x2k1 : g_x2k0)[(size_t)t * Fn + f] = x2;
        }
    }
}

// -------- combine + split weighted x2 for down GEMM ------------------------
__global__ __launch_bounds__(256) void combine_split_x2()
{
    int t = blockIdx.x;
    float w0 = g_rw[t * 2], w1 = g_rw[t * 2 + 1];
    __nv_bfloat16* d = g_x2s + (size_t)t * 3 * Fn;
    const float* s0 = g_x2k0 + (size_t)t * Fn;
    const float* s1 = g_x2k1 + (size_t)t * Fn;
    for (int f = threadIdx.x; f < Fn; f += 256) {
        float v = w0 * s0[f] + w1 * s1[f];
        __nv_bfloat16 hi = __float2bfloat16(v);
        __nv_bfloat16 lo = __float2bfloat16(v - __bfloat162float(hi));
        d[f] = hi;
        d[Fn + f] = hi;
        d[2 * Fn + f] = lo;
    }
}

// -------- grouped a2: a2[id][r] = x2_k[t] . A2[e][r]  (CH=32) --------------
#define CH2 32
__global__ __launch_bounds__(256) void a2_grouped(const float* __restrict__ A2)
{
    int e, start, nent;
    if (!find_chunk(blockIdx.x, CH2, e, start, nent)) return;
    __shared__ float xs[CH2][129];
    __shared__ float as[Rn][129];
    __shared__ int ids[CH2];
    int tid = threadIdx.x;
    if (tid < CH2)
        ids[tid] = (tid < nent) ? g_list[start + tid] : g_list[start];
    __syncthreads();

    int entry = tid >> 3, rg = tid & 7;
    float acc[4] = {0.f, 0.f, 0.f, 0.f};
    int myid = ids[entry];

    for (int f0 = 0; f0 < Fn; f0 += 128) {
#pragma unroll
        for (int i = 0; i < 16; i++) {
            int q = tid + i * 256;
            int row = q >> 7, col = q & 127;
            int id = ids[row];
            const float* src = (id & 1) ? g_x2k1 : g_x2k0;
            xs[row][col] = src[(size_t)(id >> 1) * Fn + f0 + col];
        }
#pragma unroll
        for (int i = 0; i < 16; i++) {
            int q = tid + i * 256;
            int row = q >> 7, col = q & 127;
            as[row][col] = A2[(size_t)(e * Rn + row) * Fn + f0 + col];
        }
        __syncthreads();
#pragma unroll 4
        for (int h = 0; h < 128; h++) {
            float xv = xs[entry][h];
#pragma unroll
            for (int j = 0; j < 4; j++)
                acc[j] += xv * as[rg + 8 * j][h];
        }
        __syncthreads();
    }
    if (entry < nent) {
#pragma unroll
        for (int j = 0; j < 4; j++)
            g_a2[(size_t)myid * Rn + rg + 8 * j] = acc[j];
    }
}

// -------- grouped final: l2k[t][h] = rw * (B2[e][h] . a2)  (CH=64) ---------
#define CHL 64
__global__ __launch_bounds__(256) void final_grouped(const float* __restrict__ B2)
{
    int e, start, nent;
    if (!find_chunk(blockIdx.x, CHL, e, start, nent)) return;
    __shared__ float a2s[CHL][Rn];
    __shared__ float ws[CHL];
    __shared__ int ids[CHL];
    int tid = threadIdx.x;
    if (tid < CHL) {
        int id = (tid < nent) ? g_list[start + tid] : g_list[start];
        ids[tid] = id;
        ws[tid] = g_rw[id];
    }
    __syncthreads();
#pragma unroll
    for (int i = 0; i < 8; i++) {
        int q = tid + i * 256;
        int en = q >> 5, r = q & 31;
        a2s[en][r] = g_a2[(size_t)ids[en] * Rn + r];
    }
    __syncthreads();

    for (int h0 = 0; h0 < Hn; h0 += 256) {
        int h = h0 + tid;
        float b2r[Rn];
        const float4* p2 = (const float4*)(B2 + ((size_t)e * Hn + h) * Rn);
#pragma unroll
        for (int q = 0; q < 8; q++) {
            float4 v = p2[q];
            b2r[q * 4 + 0] = v.x; b2r[q * 4 + 1] = v.y;
            b2r[q * 4 + 2] = v.z; b2r[q * 4 + 3] = v.w;
        }
        for (int en = 0; en < nent; en++) {
            int id = ids[en];
            int t = id >> 1, kk = id & 1;
            float l2 = 0.f;
#pragma unroll
            for (int r = 0; r < Rn; r++) l2 += b2r[r] * a2s[en][r];
            (kk ? g_l2k1 : g_l2k0)[(size_t)t * Hn + h] = ws[en] * l2;
        }
    }
}

// -------- add lora2 contributions into out ---------------------------------
__global__ __launch_bounds__(256) void add_out(float* __restrict__ out)
{
    int i = (blockIdx.x * 256 + threadIdx.x) * 4;
    float4 o = *(float4*)(out + i);
    float4 a = *(const float4*)(g_l2k0 + i);
    float4 b = *(const float4*)(g_l2k1 + i);
    o.x += a.x + b.x; o.y += a.y + b.y;
    o.z += a.z + b.z; o.w += a.w + b.w;
    *(float4*)(out + i) = o;
}

// ---------------------------------------------------------------------------
extern "C" void kernel_launch(void* const* d_in, const int* in_sizes, int n_in,
                              void* d_out, int out_size)
{
    (void)in_sizes; (void)n_in; (void)out_size;
    const float* x  = (const float*)d_in[0];
    const float* Wg = (const float*)d_in[1];
    const float* W1 = (const float*)d_in[2];
    const float* W2 = (const float*)d_in[3];
    const float* W3 = (const float*)d_in[4];
    const float* A1 = (const float*)d_in[5];
    const float* B1 = (const float*)d_in[6];
    const float* A2 = (const float*)d_in[7];
    const float* B2 = (const float*)d_in[8];
    const float* A3 = (const float*)d_in[9];
    const float* B3 = (const float*)d_in[10];
    float* out = (float*)d_out;

    float *base1, *base3;
    __nv_bfloat16 *xs, *w1s, *w3s, *w2s, *x2s;
    cudaGetSymbolAddress((void**)&base1, g_base1);
    cudaGetSymbolAddress((void**)&base3, g_base3);
    cudaGetSymbolAddress((void**)&xs,  g_xs);
    cudaGetSymbolAddress((void**)&w1s, g_w1s);
    cudaGetSymbolAddress((void**)&w3s, g_w3s);
    cudaGetSymbolAddress((void**)&w2s, g_w2s);
    cudaGetSymbolAddress((void**)&x2s, g_x2s);

    cudaFuncSetAttribute(gemm_bf16, cudaFuncAttributeMaxDynamicSharedMemorySize,
                         SMEM_TOTAL);

    gate_kernel<<<Tn, 256>>>(x, Wg);
    hist_kernel<<<1, 256>>>();
    scatter_kernel<<<(Tn * Kn + 255) / 256, 256>>>();

    a13_grouped<<<Tn * Kn / CHA + En, 256>>>(x, A1, A3);

    split_kernel<<<2048, 256>>>(x,  xs,  Tn, Hn, 0);
    split_kernel<<<2048, 256>>>(W1, w1s, Fn, Hn, 1);
    split_kernel<<<2048, 256>>>(W3, w3s, Fn, Hn, 1);
    split_kernel<<<2048, 256>>>(W2, w2s, Hn, Fn, 1);

    gemm_bf16<<<dim3(Fn / GBN, Tn / GBM), 256, SMEM_TOTAL>>>(xs, w1s, base1, Fn, 3 * Hn);
    gemm_bf16<<<dim3(Fn / GBN, Tn / GBM), 256, SMEM_TOTAL>>>(xs, w3s, base3, Fn, 3 * Hn);

    fuse_grouped<<<Tn * Kn / CHF + En, 256>>>(B1, B3);
    combine_split_x2<<<Tn, 256>>>();
    a2_grouped<<<Tn * Kn / CH2 + En, 256>>>(A2);

    gemm_bf16<<<dim3(Hn / GBN, Tn / GBM), 256, SMEM_TOTAL>>>(x2s, w2s, out, Hn, 3 * Fn);

    final_grouped<<<Tn * Kn / CHL + En, 256>>>(B2);
    add_out<<<Tn * Hn / 1024, 256>>>(out);
}

// round 6
// speedup vs baseline: 2.2166x; 1.0746x over previous
#include <cuda_runtime.h>
#include <cuda_bf16.h>
#include <math.h>
#include <stdint.h>

// Problem dims
#define Tn 2048   // tokens = B*S
#define Hn 2048   // hidden
#define Fn 7168   // ffn
#define En 8      // experts
#define Rn 32     // lora rank
#define Kn 2      // top-k

// HMMA GEMM tiling: 128x256, 512 threads, 3 stages
#define GBM 128
#define GBN 256
#define KBE 64                     // bf16 K elems per stage = 128B rows (SW128)
#define STAGES 3
#define A_TILE_B (GBM * 128)       // 16384
#define B_TILE_B (GBN * 128)       // 32768
#define STAGE_B  (A_TILE_B + B_TILE_B)       // 49152
#define SMEM_TOTAL (STAGES * STAGE_B)        // 147456

#define SWZ(o) ((o) ^ (((o) >> 3) & 0x70))

// ---------------- scratch (device globals) ---------------------------------
__device__ __align__(256) float g_base1[Tn * Fn];
__device__ __align__(256) float g_base3[Tn * Fn];
__device__ __align__(256) float g_x2k0[Tn * Fn];
__device__ __align__(256) float g_x2k1[Tn * Fn];
__device__ __align__(256) float g_l2k0[Tn * Hn];
__device__ __align__(256) float g_l2k1[Tn * Hn];
__device__ __align__(256) __nv_bfloat16 g_xs [Tn * 3 * Hn];   // x split  [hi,hi,lo]
__device__ __align__(256) __nv_bfloat16 g_w1s[Fn * 3 * Hn];   // W1 split [hi,lo,hi]
__device__ __align__(256) __nv_bfloat16 g_w3s[Fn * 3 * Hn];   // W3 split [hi,lo,hi]
__device__ __align__(256) __nv_bfloat16 g_w2s[Hn * 3 * Fn];   // W2 split [hi,lo,hi]
__device__ __align__(256) __nv_bfloat16 g_x2s[Tn * 3 * Fn];   // weighted x2 [hi,hi,lo]
__device__ int   g_sel[Tn * Kn];
__device__ float g_rw [Tn * Kn];
__device__ float g_a1 [Tn * Kn * Rn];
__device__ float g_a3 [Tn * Kn * Rn];
__device__ float g_a2 [Tn * Kn * Rn];
// expert grouping
__device__ int g_off [En + 1];
__device__ int g_cur [En];
__device__ int g_list[Tn * Kn];

// ---------------- helpers ---------------------------------------------------
__device__ __forceinline__ uint32_t smem_u32(const void* p) {
    uint32_t a;
    asm("{ .reg .u64 t; cvta.to.shared.u64 t, %1; cvt.u32.u64 %0, t; }"
        : "=r"(a) : "l"(p));
    return a;
}

__device__ __forceinline__ float warp_sum(float v) {
#pragma unroll
    for (int o = 16; o; o >>= 1) v += __shfl_xor_sync(0xffffffffu, v, o);
    return v;
}

__device__ __forceinline__ bool find_chunk(int b, int CH, int& e, int& start,
                                           int& nent) {
    int acc = 0;
    for (int ee = 0; ee < En; ee++) {
        int o0 = g_off[ee], o1 = g_off[ee + 1];
        int cnt = o1 - o0;
        int nch = (cnt + CH - 1) / CH;
        if (b < acc + nch) {
            e = ee;
            start = o0 + (b - acc) * CH;
            nent = min(CH, o1 - start);
            return true;
        }
        acc += nch;
    }
    return false;
}

#define LDSM4(r0, r1, r2, r3, addr) \
    asm volatile("ldmatrix.sync.aligned.m8n8.x4.shared.b16 {%0,%1,%2,%3}, [%4];" \
                 : "=r"(r0), "=r"(r1), "=r"(r2), "=r"(r3) : "r"(addr))

#define MMA16816(c, a, b0, b1) \
    asm volatile("mma.sync.aligned.m16n8k16.row.col.f32.bf16.bf16.f32 " \
                 "{%0,%1,%2,%3}, {%4,%5,%6,%7}, {%8,%9}, {%0,%1,%2,%3};" \
                 : "+f"((c)[0]), "+f"((c)[1]), "+f"((c)[2]), "+f"((c)[3]) \
                 : "r"((a)[0]), "r"((a)[1]), "r"((a)[2]), "r"((a)[3]), \
                   "r"(b0), "r"(b1))

// ---------------- bf16 hi/lo split (row per block, no div/mod) -------------
// mode 0 (A side): [hi, hi, lo]; mode 1 (B side): [hi, lo, hi]
__global__ __launch_bounds__(256) void split_kernel(
    const float* __restrict__ src, __nv_bfloat16* __restrict__ dst,
    int cols, int bmode)
{
    int r = blockIdx.x;
    const float* s = src + (size_t)r * cols;
    __nv_bfloat16* d = dst + (size_t)r * (3 * cols);
    for (int c = threadIdx.x * 4; c < cols; c += 256 * 4) {
        float4 v = *(const float4*)(s + c);
        __nv_bfloat16 h0 = __float2bfloat16(v.x);
        __nv_bfloat16 h1 = __float2bfloat16(v.y);
        __nv_bfloat16 h2 = __float2bfloat16(v.z);
        __nv_bfloat16 h3 = __float2bfloat16(v.w);
        __nv_bfloat16 l0 = __float2bfloat16(v.x - __bfloat162float(h0));
        __nv_bfloat16 l1 = __float2bfloat16(v.y - __bfloat162float(h1));
        __nv_bfloat16 l2 = __float2bfloat16(v.z - __bfloat162float(h2));
        __nv_bfloat16 l3 = __float2bfloat16(v.w - __bfloat162float(h3));
        __nv_bfloat162 hA = __halves2bfloat162(h0, h1);
        __nv_bfloat162 hB = __halves2bfloat162(h2, h3);
        __nv_bfloat162 lA = __halves2bfloat162(l0, l1);
        __nv_bfloat162 lB = __halves2bfloat162(l2, l3);
        *(__nv_bfloat162*)(d + c)     = hA;
        *(__nv_bfloat162*)(d + c + 2) = hB;
        *(__nv_bfloat162*)(d + cols + c)     = bmode ? lA : hA;
        *(__nv_bfloat162*)(d + cols + c + 2) = bmode ? lB : hB;
        *(__nv_bfloat162*)(d + 2 * cols + c)     = bmode ? hA : lA;
        *(__nv_bfloat162*)(d + 2 * cols + c + 2) = bmode ? hB : lB;
    }
}

// ---------------- GEMM stage loader (cp.async, SW128) ----------------------
__device__ __forceinline__ void load_stage(
    uint32_t sb, const __nv_bfloat16* Ab, const __nv_bfloat16* Bb,
    int Kp, int it, int stage, int tid)
{
    uint32_t st = sb + stage * STAGE_B;
    int k0 = it * KBE;
#pragma unroll
    for (int i = 0; i < 6; i++) {
        int c = tid + i * 512;          // 0..3071
        uint32_t soff;
        const __nv_bfloat16* g;
        if (c < 1024) {                 // A: 128 rows x 8 chunks
            int row = c >> 3, j = c & 7;
            soff = st + SWZ(row * 128 + j * 16);
            g = Ab + (size_t)row * Kp + k0 + j * 8;
        } else {                        // B: 256 rows x 8 chunks
            int cc = c - 1024;
            int row = cc >> 3, j = cc & 7;
            soff = st + A_TILE_B + SWZ(row * 128 + j * 16);
            g = Bb + (size_t)row * Kp + k0 + j * 8;
        }
        asm volatile("cp.async.cg.shared.global [%0], [%1], 16;"
                     :: "r"(soff), "l"(g) : "memory");
    }
}

// ---------------- HMMA bf16 GEMM: C[M,N] = A[M,Kp] @ B[N,Kp]^T -------------
__global__ __launch_bounds__(512, 1) void gemm_bf16(
    const __nv_bfloat16* __restrict__ A, const __nv_bfloat16* __restrict__ B,
    float* __restrict__ C, int N, int Kp)
{
    extern __shared__ __align__(1024) char smem[];
    uint32_t sb = smem_u32(smem);
    int tid = threadIdx.x, wid = tid >> 5, lane = tid & 31;
    int wm = wid & 3, wn = wid >> 2;       // 4 warps in M, 4 in N
    int bx = blockIdx.x, by = blockIdx.y;
    const int niter = Kp / KBE;

    const __nv_bfloat16* Ab = A + (size_t)(by * GBM) * Kp;
    const __nv_bfloat16* Bb = B + (size_t)(bx * GBN) * Kp;

    // prologue: fill STAGES-1 stages
#pragma unroll
    for (int it = 0; it < STAGES - 1; it++) {
        load_stage(sb, Ab, Bb, Kp, it, it, tid);
        asm volatile("cp.async.commit_group;" ::: "memory");
    }

    float acc[2][8][4];
#pragma unroll
    for (int mi = 0; mi < 2; mi++)
#pragma unroll
        for (int nj = 0; nj < 8; nj++)
#pragma unroll
            for (int q = 0; q < 4; q++) acc[mi][nj][q] = 0.f;

    int gq = lane >> 3, rr = lane & 7;
    int kc = gq >> 1;
    uint32_t aRow[2]; int aXor[2];
#pragma unroll
    for (int mi = 0; mi < 2; mi++) {
        int m = wm * 32 + mi * 16 + (gq & 1) * 8 + rr;
        aRow[mi] = (uint32_t)(m * 128);
        aXor[mi] = m & 7;
    }
    uint32_t bRow[4]; int bXor[4];
#pragma unroll
    for (int ni = 0; ni < 4; ni++) {
        int n = wn * 64 + ni * 16 + (gq & 1) * 8 + rr;
        bRow[ni] = (uint32_t)(A_TILE_B + n * 128);
        bXor[ni] = n & 7;
    }

    int s = 0;
    for (int it = 0; it < niter; it++) {
        asm volatile("cp.async.wait_group %0;" :: "n"(STAGES - 2) : "memory");
        __syncthreads();
        int jt = it + STAGES - 1;
        if (jt < niter) {
            int sj = jt - (jt / STAGES) * STAGES;
            load_stage(sb, Ab, Bb, Kp, jt, sj, tid);
        }
        asm volatile("cp.async.commit_group;" ::: "memory");

        uint32_t stb = sb + s * STAGE_B;
        s++; if (s == STAGES) s = 0;
#pragma unroll
        for (int ks = 0; ks < 4; ks++) {
            uint32_t a[2][4];
#pragma unroll
            for (int mi = 0; mi < 2; mi++) {
                uint32_t ad = stb + aRow[mi]
                            + (uint32_t)((((ks << 1) + kc) ^ aXor[mi]) << 4);
                LDSM4(a[mi][0], a[mi][1], a[mi][2], a[mi][3], ad);
            }
            uint32_t b[4][4];
#pragma unroll
            for (int ni = 0; ni < 4; ni++) {
                uint32_t bd = stb + bRow[ni]
                            + (uint32_t)((((ks << 1) + kc) ^ bXor[ni]) << 4);
                LDSM4(b[ni][0], b[ni][1], b[ni][2], b[ni][3], bd);
            }
#pragma unroll
            for (int mi = 0; mi < 2; mi++)
#pragma unroll
                for (int ni = 0; ni < 4; ni++) {
                    MMA16816(acc[mi][ni * 2],     a[mi], b[ni][0], b[ni][2]);
                    MMA16816(acc[mi][ni * 2 + 1], a[mi], b[ni][1], b[ni][3]);
                }
        }
        __syncthreads();
    }

    int gid = lane >> 2, tig = lane & 3;
#pragma unroll
    for (int mi = 0; mi < 2; mi++) {
        int row = by * GBM + wm * 32 + mi * 16 + gid;
#pragma unroll
        for (int nj = 0; nj < 8; nj++) {
            float* p = C + (size_t)row * N + bx * GBN + wn * 64 + nj * 8 + tig * 2;
            *(float2*)p = make_float2(acc[mi][nj][0], acc[mi][nj][1]);
            *(float2*)(p + (size_t)8 * N) = make_float2(acc[mi][nj][2], acc[mi][nj][3]);
        }
    }
}

// ---------------- K1: gate -------------------------------------------------
__global__ __launch_bounds__(256) void gate_kernel(
    const float* __restrict__ x, const float* __restrict__ Wg)
{
    int t = blockIdx.x;
    int tid = threadIdx.x;
    int w = tid >> 5, lane = tid & 31;
    const float* xr = x + (size_t)t * Hn;
    const float* wr = Wg + (size_t)w * Hn;
    float s = 0.f;
    for (int h = lane * 4; h < Hn; h += 32 * 4) {
        float4 xv = *(const float4*)(xr + h);
        float4 wv = *(const float4*)(wr + h);
        s += xv.x * wv.x + xv.y * wv.y + xv.z * wv.z + xv.w * wv.w;
    }
    s = warp_sum(s);
    __shared__ float logits[En];
    if (lane == 0) logits[w] = s;
    __syncthreads();
    if (tid == 0) {
        int i0 = 0; float l0 = logits[0];
#pragma unroll
        for (int e = 1; e < En; e++) if (logits[e] > l0) { l0 = logits[e]; i0 = e; }
        int i1 = -1; float l1 = -3.0e38f;
#pragma unroll
        for (int e = 0; e < En; e++) if (e != i0 && logits[e] > l1) { l1 = logits[e]; i1 = e; }
        float r0 = 1.f / (1.f + expf(l1 - l0));
        g_sel[t * 2 + 0] = i0;
        g_sel[t * 2 + 1] = i1;
        g_rw [t * 2 + 0] = r0;
        g_rw [t * 2 + 1] = 1.f - r0;
    }
}

// ---------------- expert grouping ------------------------------------------
__global__ __launch_bounds__(256) void hist_kernel()
{
    __shared__ int hc[En];
    int tid = threadIdx.x;
    if (tid < En) hc[tid] = 0;
    __syncthreads();
    for (int i = tid; i < Tn * Kn; i += 256)
        atomicAdd(&hc[g_sel[i]], 1);
    __syncthreads();
    if (tid == 0) {
        int off = 0;
        for (int e = 0; e < En; e++) {
            g_off[e] = off;
            g_cur[e] = off;
            off += hc[e];
        }
        g_off[En] = off;
    }
}

__global__ __launch_bounds__(256) void scatter_kernel()
{
    int i = blockIdx.x * 256 + threadIdx.x;
    if (i < Tn * Kn) {
        int e = g_sel[i];
        int pos = atomicAdd(&g_cur[e], 1);
        g_list[pos] = i;
    }
}

// -------- grouped a1/a3 (CH=8 entries, 256 thr = 8 entries x 32 rg) --------
#define CHA 8
__global__ __launch_bounds__(256) void a13_grouped(
    const float* __restrict__ x, const float* __restrict__ A1,
    const float* __restrict__ A3)
{
    int e, start, nent;
    if (!find_chunk(blockIdx.x, CHA, e, start, nent)) return;
    __shared__ float xs[CHA][129];
    __shared__ float as[64][129];
    __shared__ int ids[CHA];
    int tid = threadIdx.x;
    if (tid < CHA)
        ids[tid] = (tid < nent) ? g_list[start + tid] : g_list[start];
    __syncthreads();

    int entry = tid >> 5, rg = tid & 31;
    float acc[2] = {0.f, 0.f};
    int myid = ids[entry];

    for (int h0 = 0; h0 < Hn; h0 += 128) {
        // x rows (8 x 128)
#pragma unroll
        for (int i = 0; i < 4; i++) {
            int q = tid + i * 256;
            int row = q >> 7, col = q & 127;
            xs[row][col] = x[(size_t)(ids[row] >> 1) * Hn + h0 + col];
        }
        // A rows (64 x 128): rows 0-31 A1, 32-63 A3
#pragma unroll
        for (int i = 0; i < 32; i++) {
            int q = tid + i * 256;
            int row = q >> 7, col = q & 127;
            const float* src = (row < 32)
                ? A1 + ((size_t)(e * Rn + row) * Hn + h0 + col)
                : A3 + ((size_t)(e * Rn + row - 32) * Hn + h0 + col);
            as[row][col] = *src;
        }
        __syncthreads();
#pragma unroll 8
        for (int h = 0; h < 128; h++) {
            float xv = xs[entry][h];
            acc[0] += xv * as[rg][h];
            acc[1] += xv * as[rg + 32][h];
        }
        __syncthreads();
    }
    if (entry < nent) {
        g_a1[(size_t)myid * Rn + rg] = acc[0];
        g_a3[(size_t)myid * Rn + rg] = acc[1];
    }
}

// -------- grouped fuse (CH=32) ---------------------------------------------
#define CHF 32
__global__ __launch_bounds__(256) void fuse_grouped(
    const float* __restrict__ B1, const float* __restrict__ B3)
{
    int e, start, nent;
    if (!find_chunk(blockIdx.x, CHF, e, start, nent)) return;
    __shared__ float a1s[CHF][Rn];
    __shared__ float a3s[CHF][Rn];
    __shared__ int ids[CHF];
    int tid = threadIdx.x;
    if (tid < CHF)
        ids[tid] = (tid < nent) ? g_list[start + tid] : g_list[start];
    __syncthreads();
#pragma unroll
    for (int i = 0; i < 4; i++) {
        int q = tid + i * 256;
        int en = q >> 5, r = q & 31;
        int id = ids[en];
        a1s[en][r] = g_a1[(size_t)id * Rn + r];
        a3s[en][r] = g_a3[(size_t)id * Rn + r];
    }
    __syncthreads();

    for (int f0 = 0; f0 < Fn; f0 += 256) {
        int f = f0 + tid;
        float b1r[Rn], b3r[Rn];
        const float4* p1 = (const float4*)(B1 + ((size_t)e * Fn + f) * Rn);
        const float4* p3 = (const float4*)(B3 + ((size_t)e * Fn + f) * Rn);
#pragma unroll
        for (int q = 0; q < 8; q++) {
            float4 v1 = p1[q], v3 = p3[q];
            b1r[q * 4 + 0] = v1.x; b1r[q * 4 + 1] = v1.y;
            b1r[q * 4 + 2] = v1.z; b1r[q * 4 + 3] = v1.w;
            b3r[q * 4 + 0] = v3.x; b3r[q * 4 + 1] = v3.y;
            b3r[q * 4 + 2] = v3.z; b3r[q * 4 + 3] = v3.w;
        }
        for (int en = 0; en < nent; en++) {
            int id = ids[en];
            int t = id >> 1, kk = id & 1;
            float l1 = 0.f, l3 = 0.f;
#pragma unroll
            for (int r = 0; r < Rn; r++) {
                l1 += b1r[r] * a1s[en][r];
                l3 += b3r[r] * a3s[en][r];
            }
            float x1 = g_base1[(size_t)t * Fn + f] + l1;
            float x3 = g_base3[(size_t)t * Fn + f] + l3;
            float sig = 1.f / (1.f + expf(-x1));
            float x2 = x1 * sig * x3;
            (kk ? g_x2k1 : g_x2k0)[(size_t)t * Fn + f] = x2;
        }
    }
}

// -------- combine + split weighted x2 --------------------------------------
__global__ __launch_bounds__(256) void combine_split_x2()
{
    int t = blockIdx.x;
    float w0 = g_rw[t * 2], w1 = g_rw[t * 2 + 1];
    __nv_bfloat16* d = g_x2s + (size_t)t * 3 * Fn;
    const float* s0 = g_x2k0 + (size_t)t * Fn;
    const float* s1 = g_x2k1 + (size_t)t * Fn;
    for (int f = threadIdx.x; f < Fn; f += 256) {
        float v = w0 * s0[f] + w1 * s1[f];
        __nv_bfloat16 hi = __float2bfloat16(v);
        __nv_bfloat16 lo = __float2bfloat16(v - __bfloat162float(hi));
        d[f] = hi;
        d[Fn + f] = hi;
        d[2 * Fn + f] = lo;
    }
}

// -------- grouped a2 (CH=32) -----------------------------------------------
#define CH2 32
__global__ __launch_bounds__(256) void a2_grouped(const float* __restrict__ A2)
{
    int e, start, nent;
    if (!find_chunk(blockIdx.x, CH2, e, start, nent)) return;
    __shared__ float xs[CH2][129];
    __shared__ float as[Rn][129];
    __shared__ int ids[CH2];
    int tid = threadIdx.x;
    if (tid < CH2)
        ids[tid] = (tid < nent) ? g_list[start + tid] : g_list[start];
    __syncthreads();

    int entry = tid >> 3, rg = tid & 7;
    float acc[4] = {0.f, 0.f, 0.f, 0.f};
    int myid = ids[entry];

    for (int f0 = 0; f0 < Fn; f0 += 128) {
#pragma unroll
        for (int i = 0; i < 16; i++) {
            int q = tid + i * 256;
            int row = q >> 7, col = q & 127;
            int id = ids[row];
            const float* src = (id & 1) ? g_x2k1 : g_x2k0;
            xs[row][col] = src[(size_t)(id >> 1) * Fn + f0 + col];
        }
#pragma unroll
        for (int i = 0; i < 16; i++) {
            int q = tid + i * 256;
            int row = q >> 7, col = q & 127;
            as[row][col] = A2[(size_t)(e * Rn + row) * Fn + f0 + col];
        }
        __syncthreads();
#pragma unroll 4
        for (int h = 0; h < 128; h++) {
            float xv = xs[entry][h];
#pragma unroll
            for (int j = 0; j < 4; j++)
                acc[j] += xv * as[rg + 8 * j][h];
        }
        __syncthreads();
    }
    if (entry < nent) {
#pragma unroll
        for (int j = 0; j < 4; j++)
            g_a2[(size_t)myid * Rn + rg + 8 * j] = acc[j];
    }
}

// -------- grouped final (CH=64) --------------------------------------------
#define CHL 64
__global__ __launch_bounds__(256) void final_grouped(const float* __restrict__ B2)
{
    int e, start, nent;
    if (!find_chunk(blockIdx.x, CHL, e, start, nent)) return;
    __shared__ float a2s[CHL][Rn];
    __shared__ float ws[CHL];
    __shared__ int ids[CHL];
    int tid = threadIdx.x;
    if (tid < CHL) {
        int id = (tid < nent) ? g_list[start + tid] : g_list[start];
        ids[tid] = id;
        ws[tid] = g_rw[id];
    }
    __syncthreads();
#pragma unroll
    for (int i = 0; i < 8; i++) {
        int q = tid + i * 256;
        int en = q >> 5, r = q & 31;
        a2s[en][r] = g_a2[(size_t)ids[en] * Rn + r];
    }
    __syncthreads();

    for (int h0 = 0; h0 < Hn; h0 += 256) {
        int h = h0 + tid;
        float b2r[Rn];
        const float4* p2 = (const float4*)(B2 + ((size_t)e * Hn + h) * Rn);
#pragma unroll
        for (int q = 0; q < 8; q++) {
            float4 v = p2[q];
            b2r[q * 4 + 0] = v.x; b2r[q * 4 + 1] = v.y;
            b2r[q * 4 + 2] = v.z; b2r[q * 4 + 3] = v.w;
        }
        for (int en = 0; en < nent; en++) {
            int id = ids[en];
            int t = id >> 1, kk = id & 1;
            float l2 = 0.f;
#pragma unroll
            for (int r = 0; r < Rn; r++) l2 += b2r[r] * a2s[en][r];
            (kk ? g_l2k1 : g_l2k0)[(size_t)t * Hn + h] = ws[en] * l2;
        }
    }
}

// -------- add lora2 contributions into out ---------------------------------
__global__ __launch_bounds__(256) void add_out(float* __restrict__ out)
{
    int i = (blockIdx.x * 256 + threadIdx.x) * 4;
    float4 o = *(float4*)(out + i);
    float4 a = *(const float4*)(g_l2k0 + i);
    float4 b = *(const float4*)(g_l2k1 + i);
    o.x += a.x + b.x; o.y += a.y + b.y;
    o.z += a.z + b.z; o.w += a.w + b.w;
    *(float4*)(out + i) = o;
}

// ---------------------------------------------------------------------------
extern "C" void kernel_launch(void* const* d_in, const int* in_sizes, int n_in,
                              void* d_out, int out_size)
{
    (void)in_sizes; (void)n_in; (void)out_size;
    const float* x  = (const float*)d_in[0];
    const float* Wg = (const float*)d_in[1];
    const float* W1 = (const float*)d_in[2];
    const float* W2 = (const float*)d_in[3];
    const float* W3 = (const float*)d_in[4];
    const float* A1 = (const float*)d_in[5];
    const float* B1 = (const float*)d_in[6];
    const float* A2 = (const float*)d_in[7];
    const float* B2 = (const float*)d_in[8];
    const float* A3 = (const float*)d_in[9];
    const float* B3 = (const float*)d_in[10];
    float* out = (float*)d_out;

    float *base1, *base3;
    __nv_bfloat16 *xs, *w1s, *w3s, *w2s, *x2s;
    cudaGetSymbolAddress((void**)&base1, g_base1);
    cudaGetSymbolAddress((void**)&base3, g_base3);
    cudaGetSymbolAddress((void**)&xs,  g_xs);
    cudaGetSymbolAddress((void**)&w1s, g_w1s);
    cudaGetSymbolAddress((void**)&w3s, g_w3s);
    cudaGetSymbolAddress((void**)&w2s, g_w2s);
    cudaGetSymbolAddress((void**)&x2s, g_x2s);

    cudaFuncSetAttribute(gemm_bf16, cudaFuncAttributeMaxDynamicSharedMemorySize,
                         SMEM_TOTAL);

    gate_kernel<<<Tn, 256>>>(x, Wg);
    hist_kernel<<<1, 256>>>();
    scatter_kernel<<<(Tn * Kn + 255) / 256, 256>>>();

    a13_grouped<<<Tn * Kn / CHA + En, 256>>>(x, A1, A3);

    split_kernel<<<Tn, 256>>>(x,  xs,  Hn, 0);
    split_kernel<<<Fn, 256>>>(W1, w1s, Hn, 1);
    split_kernel<<<Fn, 256>>>(W3, w3s, Hn, 1);
    split_kernel<<<Hn, 256>>>(W2, w2s, Fn, 1);

    gemm_bf16<<<dim3(Fn / GBN, Tn / GBM), 512, SMEM_TOTAL>>>(xs, w1s, base1, Fn, 3 * Hn);
    gemm_bf16<<<dim3(Fn / GBN, Tn / GBM), 512, SMEM_TOTAL>>>(xs, w3s, base3, Fn, 3 * Hn);

    fuse_grouped<<<Tn * Kn / CHF + En, 256>>>(B1, B3);
    combine_split_x2<<<Tn, 256>>>();
    a2_grouped<<<Tn * Kn / CH2 + En, 256>>>(A2);

    gemm_bf16<<<dim3(Hn / GBN, Tn / GBM), 512, SMEM_TOTAL>>>(x2s, w2s, out, Hn, 3 * Fn);

    final_grouped<<<Tn * Kn / CHL + En, 256>>>(B2);
    add_out<<<Tn * Hn / 1024, 256>>>(out);
}

// round 7
// speedup vs baseline: 2.6749x; 1.2068x over previous
#include <cuda_runtime.h>
#include <cuda_fp16.h>
#include <math.h>
#include <stdint.h>

// Problem dims
#define Tn 2048   // tokens = B*S
#define Hn 2048   // hidden
#define Fn 7168   // ffn
#define En 8      // experts
#define Rn 32     // lora rank
#define Kn 2      // top-k

// HMMA GEMM tiling: 128x256, 512 threads, 3 stages
#define GBM 128
#define GBN 256
#define KBE 64                     // fp16 K elems per stage = 128B rows (SW128)
#define STAGES 3
#define A_TILE_B (GBM * 128)       // 16384
#define B_TILE_B (GBN * 128)       // 32768
#define STAGE_B  (A_TILE_B + B_TILE_B)       // 49152
#define SMEM_TOTAL (STAGES * STAGE_B)        // 147456

#define SWZ(o) ((o) ^ (((o) >> 3) & 0x70))

// ---------------- scratch (device globals) ---------------------------------
__device__ __align__(256) float g_base1[Tn * Fn];
__device__ __align__(256) float g_base3[Tn * Fn];
__device__ __align__(256) float g_x2k0[Tn * Fn];
__device__ __align__(256) float g_x2k1[Tn * Fn];
__device__ __align__(256) float g_l2k0[Tn * Hn];
__device__ __align__(256) float g_l2k1[Tn * Hn];
__device__ __align__(256) __half g_xs [Tn * 2 * Hn];   // x split  [hi,lo]
__device__ __align__(256) __half g_w1s[Fn * 2 * Hn];   // W1 dup  [wh,wh]
__device__ __align__(256) __half g_w3s[Fn * 2 * Hn];   // W3 dup  [wh,wh]
__device__ __align__(256) __half g_w2s[Hn * 2 * Fn];   // W2 dup  [wh,wh]
__device__ __align__(256) __half g_x2s[Tn * 2 * Fn];   // weighted x2 [hi,lo]
__device__ int   g_sel[Tn * Kn];
__device__ float g_rw [Tn * Kn];
__device__ float g_a1 [Tn * Kn * Rn];
__device__ float g_a3 [Tn * Kn * Rn];
__device__ float g_a2 [Tn * Kn * Rn];
// expert grouping
__device__ int g_off [En + 1];
__device__ int g_cur [En];
__device__ int g_list[Tn * Kn];

// ---------------- helpers ---------------------------------------------------
__device__ __forceinline__ uint32_t smem_u32(const void* p) {
    uint32_t a;
    asm("{ .reg .u64 t; cvta.to.shared.u64 t, %1; cvt.u32.u64 %0, t; }"
        : "=r"(a) : "l"(p));
    return a;
}

__device__ __forceinline__ float warp_sum(float v) {
#pragma unroll
    for (int o = 16; o; o >>= 1) v += __shfl_xor_sync(0xffffffffu, v, o);
    return v;
}

__device__ __forceinline__ bool find_chunk(int b, int CH, int& e, int& start,
                                           int& nent) {
    int acc = 0;
    for (int ee = 0; ee < En; ee++) {
        int o0 = g_off[ee], o1 = g_off[ee + 1];
        int cnt = o1 - o0;
        int nch = (cnt + CH - 1) / CH;
        if (b < acc + nch) {
            e = ee;
            start = o0 + (b - acc) * CH;
            nent = min(CH, o1 - start);
            return true;
        }
        acc += nch;
    }
    return false;
}

#define LDSM4(r0, r1, r2, r3, addr) \
    asm volatile("ldmatrix.sync.aligned.m8n8.x4.shared.b16 {%0,%1,%2,%3}, [%4];" \
                 : "=r"(r0), "=r"(r1), "=r"(r2), "=r"(r3) : "r"(addr))

#define MMA16816(c, a, b0, b1) \
    asm volatile("mma.sync.aligned.m16n8k16.row.col.f32.f16.f16.f32 " \
                 "{%0,%1,%2,%3}, {%4,%5,%6,%7}, {%8,%9}, {%0,%1,%2,%3};" \
                 : "+f"((c)[0]), "+f"((c)[1]), "+f"((c)[2]), "+f"((c)[3]) \
                 : "r"((a)[0]), "r"((a)[1]), "r"((a)[2]), "r"((a)[3]), \
                   "r"(b0), "r"(b1))

// ---------------- fp16 split kernels (row per block) -----------------------
// mode 0 (A side): [hi, lo]; mode 1 (B side): [wh, wh]
__global__ __launch_bounds__(256) void split_kernel(
    const float* __restrict__ src, __half* __restrict__ dst,
    int cols, int bmode)
{
    int r = blockIdx.x;
    const float* s = src + (size_t)r * cols;
    __half* d = dst + (size_t)r * (2 * cols);
    for (int c = threadIdx.x * 4; c < cols; c += 256 * 4) {
        float4 v = *(const float4*)(s + c);
        __half h0 = __float2half_rn(v.x);
        __half h1 = __float2half_rn(v.y);
        __half h2 = __float2half_rn(v.z);
        __half h3 = __float2half_rn(v.w);
        __half2 hA = __halves2half2(h0, h1);
        __half2 hB = __halves2half2(h2, h3);
        *(__half2*)(d + c)     = hA;
        *(__half2*)(d + c + 2) = hB;
        if (bmode) {
            *(__half2*)(d + cols + c)     = hA;
            *(__half2*)(d + cols + c + 2) = hB;
        } else {
            __half l0 = __float2half_rn(v.x - __half2float(h0));
            __half l1 = __float2half_rn(v.y - __half2float(h1));
            __half l2 = __float2half_rn(v.z - __half2float(h2));
            __half l3 = __float2half_rn(v.w - __half2float(h3));
            *(__half2*)(d + cols + c)     = __halves2half2(l0, l1);
            *(__half2*)(d + cols + c + 2) = __halves2half2(l2, l3);
        }
    }
}

// ---------------- GEMM stage loader (cp.async, SW128) ----------------------
__device__ __forceinline__ void load_stage(
    uint32_t sb, const __half* Ab, const __half* Bb,
    int Kp, int it, int stage, int tid)
{
    uint32_t st = sb + stage * STAGE_B;
    int k0 = it * KBE;
#pragma unroll
    for (int i = 0; i < 6; i++) {
        int c = tid + i * 512;          // 0..3071
        uint32_t soff;
        const __half* g;
        if (c < 1024) {                 // A: 128 rows x 8 chunks
            int row = c >> 3, j = c & 7;
            soff = st + SWZ(row * 128 + j * 16);
            g = Ab + (size_t)row * Kp + k0 + j * 8;
        } else {                        // B: 256 rows x 8 chunks
            int cc = c - 1024;
            int row = cc >> 3, j = cc & 7;
            soff = st + A_TILE_B + SWZ(row * 128 + j * 16);
            g = Bb + (size_t)row * Kp + k0 + j * 8;
        }
        asm volatile("cp.async.cg.shared.global [%0], [%1], 16;"
                     :: "r"(soff), "l"(g) : "memory");
    }
}

// ---------------- HMMA fp16 GEMM: C[M,N] = A[M,Kp] @ B[N,Kp]^T -------------
__global__ __launch_bounds__(512, 1) void gemm_f16(
    const __half* __restrict__ A, const __half* __restrict__ B,
    float* __restrict__ C, int N, int Kp)
{
    extern __shared__ __align__(1024) char smem[];
    uint32_t sb = smem_u32(smem);
    int tid = threadIdx.x, wid = tid >> 5, lane = tid & 31;
    int wm = wid & 3, wn = wid >> 2;       // 4 warps in M, 4 in N
    int bx = blockIdx.x, by = blockIdx.y;
    const int niter = Kp / KBE;

    const __half* Ab = A + (size_t)(by * GBM) * Kp;
    const __half* Bb = B + (size_t)(bx * GBN) * Kp;

#pragma unroll
    for (int it = 0; it < STAGES - 1; it++) {
        load_stage(sb, Ab, Bb, Kp, it, it, tid);
        asm volatile("cp.async.commit_group;" ::: "memory");
    }

    float acc[2][8][4];
#pragma unroll
    for (int mi = 0; mi < 2; mi++)
#pragma unroll
        for (int nj = 0; nj < 8; nj++)
#pragma unroll
            for (int q = 0; q < 4; q++) acc[mi][nj][q] = 0.f;

    int gq = lane >> 3, rr = lane & 7;
    int kc = gq >> 1;
    uint32_t aRow[2]; int aXor[2];
#pragma unroll
    for (int mi = 0; mi < 2; mi++) {
        int m = wm * 32 + mi * 16 + (gq & 1) * 8 + rr;
        aRow[mi] = (uint32_t)(m * 128);
        aXor[mi] = m & 7;
    }
    uint32_t bRow[4]; int bXor[4];
#pragma unroll
    for (int ni = 0; ni < 4; ni++) {
        int n = wn * 64 + ni * 16 + (gq & 1) * 8 + rr;
        bRow[ni] = (uint32_t)(A_TILE_B + n * 128);
        bXor[ni] = n & 7;
    }

    int s = 0;
    for (int it = 0; it < niter; it++) {
        asm volatile("cp.async.wait_group %0;" :: "n"(STAGES - 2) : "memory");
        __syncthreads();
        int jt = it + STAGES - 1;
        if (jt < niter) {
            int sj = jt - (jt / STAGES) * STAGES;
            load_stage(sb, Ab, Bb, Kp, jt, sj, tid);
        }
        asm volatile("cp.async.commit_group;" ::: "memory");

        uint32_t stb = sb + s * STAGE_B;
        s++; if (s == STAGES) s = 0;
#pragma unroll
        for (int ks = 0; ks < 4; ks++) {
            uint32_t a[2][4];
#pragma unroll
            for (int mi = 0; mi < 2; mi++) {
                uint32_t ad = stb + aRow[mi]
                            + (uint32_t)((((ks << 1) + kc) ^ aXor[mi]) << 4);
                LDSM4(a[mi][0], a[mi][1], a[mi][2], a[mi][3], ad);
            }
            uint32_t b[4][4];
#pragma unroll
            for (int ni = 0; ni < 4; ni++) {
                uint32_t bd = stb + bRow[ni]
                            + (uint32_t)((((ks << 1) + kc) ^ bXor[ni]) << 4);
                LDSM4(b[ni][0], b[ni][1], b[ni][2], b[ni][3], bd);
            }
#pragma unroll
            for (int mi = 0; mi < 2; mi++)
#pragma unroll
                for (int ni = 0; ni < 4; ni++) {
                    MMA16816(acc[mi][ni * 2],     a[mi], b[ni][0], b[ni][2]);
                    MMA16816(acc[mi][ni * 2 + 1], a[mi], b[ni][1], b[ni][3]);
                }
        }
        __syncthreads();
    }

    int gid = lane >> 2, tig = lane & 3;
#pragma unroll
    for (int mi = 0; mi < 2; mi++) {
        int row = by * GBM + wm * 32 + mi * 16 + gid;
#pragma unroll
        for (int nj = 0; nj < 8; nj++) {
            float* p = C + (size_t)row * N + bx * GBN + wn * 64 + nj * 8 + tig * 2;
            *(float2*)p = make_float2(acc[mi][nj][0], acc[mi][nj][1]);
            *(float2*)(p + (size_t)8 * N) = make_float2(acc[mi][nj][2], acc[mi][nj][3]);
        }
    }
}

// ---------------- K1: gate -------------------------------------------------
__global__ __launch_bounds__(256) void gate_kernel(
    const float* __restrict__ x, const float* __restrict__ Wg)
{
    int t = blockIdx.x;
    int tid = threadIdx.x;
    int w = tid >> 5, lane = tid & 31;
    const float* xr = x + (size_t)t * Hn;
    const float* wr = Wg + (size_t)w * Hn;
    float s = 0.f;
    for (int h = lane * 4; h < Hn; h += 32 * 4) {
        float4 xv = *(const float4*)(xr + h);
        float4 wv = *(const float4*)(wr + h);
        s += xv.x * wv.x + xv.y * wv.y + xv.z * wv.z + xv.w * wv.w;
    }
    s = warp_sum(s);
    __shared__ float logits[En];
    if (lane == 0) logits[w] = s;
    __syncthreads();
    if (tid == 0) {
        int i0 = 0; float l0 = logits[0];
#pragma unroll
        for (int e = 1; e < En; e++) if (logits[e] > l0) { l0 = logits[e]; i0 = e; }
        int i1 = -1; float l1 = -3.0e38f;
#pragma unroll
        for (int e = 0; e < En; e++) if (e != i0 && logits[e] > l1) { l1 = logits[e]; i1 = e; }
        float r0 = 1.f / (1.f + expf(l1 - l0));
        g_sel[t * 2 + 0] = i0;
        g_sel[t * 2 + 1] = i1;
        g_rw [t * 2 + 0] = r0;
        g_rw [t * 2 + 1] = 1.f - r0;
    }
}

// ---------------- expert grouping ------------------------------------------
__global__ __launch_bounds__(256) void hist_kernel()
{
    __shared__ int hc[En];
    int tid = threadIdx.x;
    if (tid < En) hc[tid] = 0;
    __syncthreads();
    for (int i = tid; i < Tn * Kn; i += 256)
        atomicAdd(&hc[g_sel[i]], 1);
    __syncthreads();
    if (tid == 0) {
        int off = 0;
        for (int e = 0; e < En; e++) {
            g_off[e] = off;
            g_cur[e] = off;
            off += hc[e];
        }
        g_off[En] = off;
    }
}

__global__ __launch_bounds__(256) void scatter_kernel()
{
    int i = blockIdx.x * 256 + threadIdx.x;
    if (i < Tn * Kn) {
        int e = g_sel[i];
        int pos = atomicAdd(&g_cur[e], 1);
        g_list[pos] = i;
    }
}

// -------- grouped a1/a3 (CH=8 entries; float4 inner loop) ------------------
#define CHA 8
#define PAD 132
__global__ __launch_bounds__(256) void a13_grouped(
    const float* __restrict__ x, const float* __restrict__ A1,
    const float* __restrict__ A3)
{
    int e, start, nent;
    if (!find_chunk(blockIdx.x, CHA, e, start, nent)) return;
    __shared__ float xs[CHA][PAD];
    __shared__ float as[64][PAD];
    __shared__ int ids[CHA];
    int tid = threadIdx.x;
    if (tid < CHA)
        ids[tid] = (tid < nent) ? g_list[start + tid] : g_list[start];
    __syncthreads();

    int entry = tid >> 5, rg = tid & 31;
    float acc0 = 0.f, acc1 = 0.f;
    int myid = ids[entry];

    for (int h0 = 0; h0 < Hn; h0 += 128) {
#pragma unroll
        for (int i = 0; i < 4; i++) {
            int q = tid + i * 256;
            int row = q >> 7, col = q & 127;
            xs[row][col] = x[(size_t)(ids[row] >> 1) * Hn + h0 + col];
        }
#pragma unroll
        for (int i = 0; i < 32; i++) {
            int q = tid + i * 256;
            int row = q >> 7, col = q & 127;
            const float* src = (row < 32)
                ? A1 + ((size_t)(e * Rn + row) * Hn + h0 + col)
                : A3 + ((size_t)(e * Rn + row - 32) * Hn + h0 + col);
            as[row][col] = *src;
        }
        __syncthreads();
#pragma unroll
        for (int h = 0; h < 128; h += 4) {
            float4 xv = *(const float4*)&xs[entry][h];
            float4 a0 = *(const float4*)&as[rg][h];
            float4 a1 = *(const float4*)&as[rg + 32][h];
            acc0 += xv.x * a0.x + xv.y * a0.y + xv.z * a0.z + xv.w * a0.w;
            acc1 += xv.x * a1.x + xv.y * a1.y + xv.z * a1.z + xv.w * a1.w;
        }
        __syncthreads();
    }
    if (entry < nent) {
        g_a1[(size_t)myid * Rn + rg] = acc0;
        g_a3[(size_t)myid * Rn + rg] = acc1;
    }
}

// -------- grouped fuse (CH=32) ---------------------------------------------
#define CHF 32
__global__ __launch_bounds__(256) void fuse_grouped(
    const float* __restrict__ B1, const float* __restrict__ B3)
{
    int e, start, nent;
    if (!find_chunk(blockIdx.x, CHF, e, start, nent)) return;
    __shared__ float a1s[CHF][Rn];
    __shared__ float a3s[CHF][Rn];
    __shared__ int ids[CHF];
    int tid = threadIdx.x;
    if (tid < CHF)
        ids[tid] = (tid < nent) ? g_list[start + tid] : g_list[start];
    __syncthreads();
#pragma unroll
    for (int i = 0; i < 4; i++) {
        int q = tid + i * 256;
        int en = q >> 5, r = q & 31;
        int id = ids[en];
        a1s[en][r] = g_a1[(size_t)id * Rn + r];
        a3s[en][r] = g_a3[(size_t)id * Rn + r];
    }
    __syncthreads();

    for (int f0 = 0; f0 < Fn; f0 += 256) {
        int f = f0 + tid;
        float b1r[Rn], b3r[Rn];
        const float4* p1 = (const float4*)(B1 + ((size_t)e * Fn + f) * Rn);
        const float4* p3 = (const float4*)(B3 + ((size_t)e * Fn + f) * Rn);
#pragma unroll
        for (int q = 0; q < 8; q++) {
            float4 v1 = p1[q], v3 = p3[q];
            b1r[q * 4 + 0] = v1.x; b1r[q * 4 + 1] = v1.y;
            b1r[q * 4 + 2] = v1.z; b1r[q * 4 + 3] = v1.w;
            b3r[q * 4 + 0] = v3.x; b3r[q * 4 + 1] = v3.y;
            b3r[q * 4 + 2] = v3.z; b3r[q * 4 + 3] = v3.w;
        }
        for (int en = 0; en < nent; en++) {
            int id = ids[en];
            int t = id >> 1, kk = id & 1;
            float l1 = 0.f, l3 = 0.f;
#pragma unroll
            for (int r = 0; r < Rn; r++) {
                l1 += b1r[r] * a1s[en][r];
                l3 += b3r[r] * a3s[en][r];
            }
            float x1 = g_base1[(size_t)t * Fn + f] + l1;
            float x3 = g_base3[(size_t)t * Fn + f] + l3;
            float sig = 1.f / (1.f + expf(-x1));
            float x2 = x1 * sig * x3;
            (kk ? g_x2k1 : g_x2k0)[(size_t)t * Fn + f] = x2;
        }
    }
}

// -------- combine + split weighted x2 (fp16 [hi,lo]) -----------------------
__global__ __launch_bounds__(256) void combine_split_x2()
{
    int t = blockIdx.x;
    float w0 = g_rw[t * 2], w1 = g_rw[t * 2 + 1];
    __half* d = g_x2s + (size_t)t * 2 * Fn;
    const float* s0 = g_x2k0 + (size_t)t * Fn;
    const float* s1 = g_x2k1 + (size_t)t * Fn;
    for (int f = threadIdx.x; f < Fn; f += 256) {
        float v = w0 * s0[f] + w1 * s1[f];
        __half hi = __float2half_rn(v);
        __half lo = __float2half_rn(v - __half2float(hi));
        d[f] = hi;
        d[Fn + f] = lo;
    }
}

// -------- grouped a2 (CH=32; float4 inner loop) ----------------------------
#define CH2 32
__global__ __launch_bounds__(256) void a2_grouped(const float* __restrict__ A2)
{
    int e, start, nent;
    if (!find_chunk(blockIdx.x, CH2, e, start, nent)) return;
    __shared__ float xs[CH2][PAD];
    __shared__ float as[Rn][PAD];
    __shared__ int ids[CH2];
    int tid = threadIdx.x;
    if (tid < CH2)
        ids[tid] = (tid < nent) ? g_list[start + tid] : g_list[start];
    __syncthreads();

    int entry = tid >> 3, rg = tid & 7;
    float acc[4] = {0.f, 0.f, 0.f, 0.f};
    int myid = ids[entry];

    for (int f0 = 0; f0 < Fn; f0 += 128) {
#pragma unroll
        for (int i = 0; i < 16; i++) {
            int q = tid + i * 256;
            int row = q >> 7, col = q & 127;
            int id = ids[row];
            const float* src = (id & 1) ? g_x2k1 : g_x2k0;
            xs[row][col] = src[(size_t)(id >> 1) * Fn + f0 + col];
        }
#pragma unroll
        for (int i = 0; i < 16; i++) {
            int q = tid + i * 256;
            int row = q >> 7, col = q & 127;
            as[row][col] = A2[(size_t)(e * Rn + row) * Fn + f0 + col];
        }
        __syncthreads();
#pragma unroll
        for (int h = 0; h < 128; h += 4) {
            float4 xv = *(const float4*)&xs[entry][h];
#pragma unroll
            for (int j = 0; j < 4; j++) {
                float4 av = *(const float4*)&as[rg + 8 * j][h];
                acc[j] += xv.x * av.x + xv.y * av.y + xv.z * av.z + xv.w * av.w;
            }
        }
        __syncthreads();
    }
    if (entry < nent) {
#pragma unroll
        for (int j = 0; j < 4; j++)
            g_a2[(size_t)myid * Rn + rg + 8 * j] = acc[j];
    }
}

// -------- grouped final (CH=64) --------------------------------------------
#define CHL 64
__global__ __launch_bounds__(256) void final_grouped(const float* __restrict__ B2)
{
    int e, start, nent;
    if (!find_chunk(blockIdx.x, CHL, e, start, nent)) return;
    __shared__ float a2s[CHL][Rn];
    __shared__ float ws[CHL];
    __shared__ int ids[CHL];
    int tid = threadIdx.x;
    if (tid < CHL) {
        int id = (tid < nent) ? g_list[start + tid] : g_list[start];
        ids[tid] = id;
        ws[tid] = g_rw[id];
    }
    __syncthreads();
#pragma unroll
    for (int i = 0; i < 8; i++) {
        int q = tid + i * 256;
        int en = q >> 5, r = q & 31;
        a2s[en][r] = g_a2[(size_t)ids[en] * Rn + r];
    }
    __syncthreads();

    for (int h0 = 0; h0 < Hn; h0 += 256) {
        int h = h0 + tid;
        float b2r[Rn];
        const float4* p2 = (const float4*)(B2 + ((size_t)e * Hn + h) * Rn);
#pragma unroll
        for (int q = 0; q < 8; q++) {
            float4 v = p2[q];
            b2r[q * 4 + 0] = v.x; b2r[q * 4 + 1] = v.y;
            b2r[q * 4 + 2] = v.z; b2r[q * 4 + 3] = v.w;
        }
        for (int en = 0; en < nent; en++) {
            int id = ids[en];
            int t = id >> 1, kk = id & 1;
            float l2 = 0.f;
#pragma unroll
            for (int r = 0; r < Rn; r++) l2 += b2r[r] * a2s[en][r];
            (kk ? g_l2k1 : g_l2k0)[(size_t)t * Hn + h] = ws[en] * l2;
        }
    }
}

// -------- add lora2 contributions into out ---------------------------------
__global__ __launch_bounds__(256) void add_out(float* __restrict__ out)
{
    int i = (blockIdx.x * 256 + threadIdx.x) * 4;
    float4 o = *(float4*)(out + i);
    float4 a = *(const float4*)(g_l2k0 + i);
    float4 b = *(const float4*)(g_l2k1 + i);
    o.x += a.x + b.x; o.y += a.y + b.y;
    o.z += a.z + b.z; o.w += a.w + b.w;
    *(float4*)(out + i) = o;
}

// ---------------------------------------------------------------------------
extern "C" void kernel_launch(void* const* d_in, const int* in_sizes, int n_in,
                              void* d_out, int out_size)
{
    (void)in_sizes; (void)n_in; (void)out_size;
    const float* x  = (const float*)d_in[0];
    const float* Wg = (const float*)d_in[1];
    const float* W1 = (const float*)d_in[2];
    const float* W2 = (const float*)d_in[3];
    const float* W3 = (const float*)d_in[4];
    const float* A1 = (const float*)d_in[5];
    const float* B1 = (const float*)d_in[6];
    const float* A2 = (const float*)d_in[7];
    const float* B2 = (const float*)d_in[8];
    const float* A3 = (const float*)d_in[9];
    const float* B3 = (const float*)d_in[10];
    float* out = (float*)d_out;

    float *base1, *base3;
    __half *xs, *w1s, *w3s, *w2s, *x2s;
    cudaGetSymbolAddress((void**)&base1, g_base1);
    cudaGetSymbolAddress((void**)&base3, g_base3);
    cudaGetSymbolAddress((void**)&xs,  g_xs);
    cudaGetSymbolAddress((void**)&w1s, g_w1s);
    cudaGetSymbolAddress((void**)&w3s, g_w3s);
    cudaGetSymbolAddress((void**)&w2s, g_w2s);
    cudaGetSymbolAddress((void**)&x2s, g_x2s);

    cudaFuncSetAttribute(gemm_f16, cudaFuncAttributeMaxDynamicSharedMemorySize,
                         SMEM_TOTAL);

    gate_kernel<<<Tn, 256>>>(x, Wg);
    hist_kernel<<<1, 256>>>();
    scatter_kernel<<<(Tn * Kn + 255) / 256, 256>>>();

    a13_grouped<<<Tn * Kn / CHA + En, 256>>>(x, A1, A3);

    split_kernel<<<Tn, 256>>>(x,  xs,  Hn, 0);   // A side [hi,lo]
    split_kernel<<<Fn, 256>>>(W1, w1s, Hn, 1);   // B side [wh,wh]
    split_kernel<<<Fn, 256>>>(W3, w3s, Hn, 1);
    split_kernel<<<Hn, 256>>>(W2, w2s, Fn, 1);

    // base1 = x @ W1^T, base3 = x @ W3^T   (fp16 2-term, K' = 2*Hn)
    gemm_f16<<<dim3(Fn / GBN, Tn / GBM), 512, SMEM_TOTAL>>>(xs, w1s, base1, Fn, 2 * Hn);
    gemm_f16<<<dim3(Fn / GBN, Tn / GBM), 512, SMEM_TOTAL>>>(xs, w3s, base3, Fn, 2 * Hn);

    fuse_grouped<<<Tn * Kn / CHF + En, 256>>>(B1, B3);
    combine_split_x2<<<Tn, 256>>>();
    a2_grouped<<<Tn * Kn / CH2 + En, 256>>>(A2);

    // down GEMM into d_out: out = (rw0*x2_0 + rw1*x2_1) @ W2^T  (K' = 2*Fn)
    gemm_f16<<<dim3(Hn / GBN, Tn / GBM), 512, SMEM_TOTAL>>>(x2s, w2s, out, Hn, 2 * Fn);

    final_grouped<<<Tn * Kn / CHL + En, 256>>>(B2);
    add_out<<<Tn * Hn / 1024, 256>>>(out);
}